// round 2
// baseline (speedup 1.0000x reference)
#include <cuda_runtime.h>
#include <cuda_bf16.h>
#include <math.h>

// ---------------- problem constants ----------------
constexpr int cT   = 2048;
constexpr int cD   = 1024;
constexpr int cV   = 32000;
constexpr int cE   = 16;
constexpr int cK   = 2;       // topk
constexpr int cCAP = 512;
constexpr int cH   = 16;
constexpr int cDH  = 64;
constexpr int cDFF = 4096;
constexpr int cHOPS= 2;

// ---------------- device scratch (no cudaMalloc allowed) ----------------
__device__ float g_h   [cT * cD];                 // hidden state [T,D]
__device__ float g_hn  [cT * cD];                 // normalized hidden
__device__ float g_cos [cT * cDH];
__device__ float g_sin [cT * cDH];
__device__ float g_logits[cT * cE];
__device__ float g_probs [cT * cE];
__device__ unsigned char g_mask[cT * cE];
__device__ int   g_kept_slot[cT * cE];            // slot index or -1
__device__ int   g_counts[cE];
__device__ int   g_etok[cE * cCAP];               // token id per slot
__device__ float g_xin [(long)cE * cCAP * cD];    // 32 MB
__device__ float g_mid [(long)cE * cCAP * cDFF];  // 128 MB
__device__ float g_eout[(long)cE * cCAP * cD];    // 32 MB

// ---------------- small kernels ----------------
__global__ void rope_init_kernel() {
    int t = blockIdx.x;
    int i = threadIdx.x;               // 0..63
    int j = 2 * (i & 31);              // 0,2,...,62
    float inv = powf(10000.0f, -(float)j / (float)cDH);
    float fr  = (float)t * inv;
    g_cos[t * cDH + i] = cosf(fr);
    g_sin[t * cDH + i] = sinf(fr);
}

__global__ void embed_gather_kernel(const int* __restrict__ ids,
                                    const float* __restrict__ ew) {
    long idx = (long)blockIdx.x * blockDim.x + threadIdx.x;
    if (idx >= (long)cT * cD) return;
    int t = (int)(idx >> 10);
    int d = (int)(idx & (cD - 1));
    g_h[idx] = ew[(long)ids[t] * cD + d];
}

// logits[t,e] = h[t,:] @ wr[:,e] ; one block per token, 16 warps (one per expert)
__global__ void router_logits_kernel(const float* __restrict__ wr) {
    int t    = blockIdx.x;
    int e    = threadIdx.x >> 5;
    int lane = threadIdx.x & 31;
    float s = 0.f;
    const float* hp = &g_h[(long)t * cD];
    for (int d = lane; d < cD; d += 32)
        s += hp[d] * wr[(long)d * cE + e];
    #pragma unroll
    for (int o = 16; o; o >>= 1) s += __shfl_down_sync(0xffffffffu, s, o);
    if (lane == 0) g_logits[t * cE + e] = s;
}

// per-token: softmax, top-2 mask, reset kept slots; also reset expert counts
__global__ void token_route_kernel() {
    int t = blockIdx.x * blockDim.x + threadIdx.x;
    if (t >= cT) return;
    float l[cE];
    #pragma unroll
    for (int e = 0; e < cE; e++) l[e] = g_logits[t * cE + e];
    // top-1 (ties -> lower index, matching jax.lax.top_k)
    int i1 = 0; float v1 = l[0];
    #pragma unroll
    for (int e = 1; e < cE; e++) if (l[e] > v1) { v1 = l[e]; i1 = e; }
    // top-2
    int i2 = -1; float v2 = -INFINITY;
    #pragma unroll
    for (int e = 0; e < cE; e++) if (e != i1 && l[e] > v2) { v2 = l[e]; i2 = e; }
    // softmax
    float sum = 0.f; float p[cE];
    #pragma unroll
    for (int e = 0; e < cE; e++) { p[e] = expf(l[e] - v1); sum += p[e]; }
    float invs = 1.0f / sum;
    #pragma unroll
    for (int e = 0; e < cE; e++) {
        g_probs[t * cE + e] = p[e] * invs;
        g_mask [t * cE + e] = (e == i1 || e == i2) ? 1 : 0;
        g_kept_slot[t * cE + e] = -1;
    }
    if (t < cE) g_counts[t] = 0;
}

// per-expert capacity-512 selection by exact rank (value desc, index asc)
__global__ void capacity_kernel() {
    int e = blockIdx.x;
    __shared__ float sg[cT];
    __shared__ unsigned char sm[cT];
    for (int t = threadIdx.x; t < cT; t += blockDim.x) {
        sg[t] = g_logits[t * cE + e];
        sm[t] = g_mask  [t * cE + e];
    }
    __syncthreads();
    for (int t = threadIdx.x; t < cT; t += blockDim.x) {
        if (!sm[t]) continue;
        float v = sg[t];
        int rank = 0;
        for (int u = 0; u < cT; u++) {
            if (sm[u] && (sg[u] > v || (sg[u] == v && u < t))) rank++;
        }
        if (rank < cCAP) {
            int s = atomicAdd(&g_counts[e], 1);
            g_etok[e * cCAP + s] = t;
            g_kept_slot[t * cE + e] = s;
        }
    }
}

// gather token hidden into expert slot buffer + apply RoPE
__global__ void gather_rope_kernel() {
    int c = blockIdx.x;
    int e = blockIdx.y;
    if (c >= g_counts[e]) return;
    int t = g_etok[e * cCAP + c];
    __shared__ float x[cD];
    for (int d = threadIdx.x; d < cD; d += blockDim.x) x[d] = g_h[(long)t * cD + d];
    __syncthreads();
    const float* cs = &g_cos[t * cDH];
    const float* sn = &g_sin[t * cDH];
    float* out = &g_xin[((long)(e * cCAP + c)) * cD];
    for (int d = threadIdx.x; d < cD; d += blockDim.x) {
        int i = d & (cDH - 1);
        float r = (i < 32) ? -x[d + 32] : x[d - 32];
        out[d] = x[d] * cs[i] + r * sn[i];
    }
}

// combine expert outputs back to tokens: h = h + sum(p*out) - rho*h
__global__ void combine_kernel() {
    int t = blockIdx.x;
    int ne = 0;
    int  ks[cK]; float kp[cK]; int ke[cK];
    float rho = 0.f;
    #pragma unroll
    for (int e = 0; e < cE; e++) {
        int s = g_kept_slot[t * cE + e];
        if (s >= 0) {
            float p = g_probs[t * cE + e];
            rho += p;
            if (ne < cK) { ke[ne] = e; ks[ne] = s; kp[ne] = p; ne++; }
        }
    }
    for (int d = threadIdx.x; d < cD; d += blockDim.x) {
        float hv = g_h[(long)t * cD + d];
        float comb = 0.f;
        for (int q = 0; q < ne; q++)
            comb += kp[q] * g_eout[((long)(ke[q] * cCAP + ks[q])) * cD + d];
        g_h[(long)t * cD + d] = hv + comb - rho * hv;
    }
}

__global__ void rmsnorm_kernel(const float* __restrict__ lns) {
    int t = blockIdx.x;
    __shared__ float red[256];
    float s = 0.f;
    for (int d = threadIdx.x; d < cD; d += 256) {
        float v = g_h[(long)t * cD + d];
        s += v * v;
    }
    red[threadIdx.x] = s;
    __syncthreads();
    #pragma unroll
    for (int o = 128; o; o >>= 1) {
        if (threadIdx.x < o) red[threadIdx.x] += red[threadIdx.x + o];
        __syncthreads();
    }
    float inv = rsqrtf(red[0] / (float)cD + 1e-6f);
    for (int d = threadIdx.x; d < cD; d += 256)
        g_hn[(long)t * cD + d] = g_h[(long)t * cD + d] * lns[d] * inv;
}

// ---------------- SGEMM 128x128x8, 256 threads, 8x8 per thread ----------------
// C[M,N] = act( A[M,K] @ B )   A row-major (lda)
// TRANSB=0: B[k*ldb + n] ; TRANSB=1: B[n*ldb + k]
// batched over blockIdx.z with strides sA/sB/sC; per-batch M from Mvec if non-null
template<int TRANSB, int ACT>
__global__ void __launch_bounds__(256, 2)
sgemm_kernel(const float* __restrict__ A, const float* __restrict__ B,
             float* __restrict__ C,
             int M, int N, int Kd, int lda, int ldb, int ldc,
             long sA, long sB, long sC, const int* __restrict__ Mvec)
{
    constexpr int BM = 128, BN = 128, BK = 8;
    int e = blockIdx.z;
    if (Mvec) M = Mvec[e];
    int bm = blockIdx.y * BM;
    if (bm >= M) return;
    int bn = blockIdx.x * BN;
    A += (long)e * sA; B += (long)e * sB; C += (long)e * sC;

    __shared__ float As[BK][BM];
    __shared__ float Bs[BK][BN];

    int tid = threadIdx.x;
    int tx = tid & 15, ty = tid >> 4;

    float acc[8][8];
    #pragma unroll
    for (int i = 0; i < 8; i++)
        #pragma unroll
        for (int j = 0; j < 8; j++) acc[i][j] = 0.f;

    int arow = tid >> 1;
    int acol = (tid & 1) * 4;
    int brow = tid >> 5;
    int bcol = (tid & 31) * 4;
    int tkk  = tid & 7;
    int tn0  = tid >> 3;

    for (int k0 = 0; k0 < Kd; k0 += BK) {
        float4 av = make_float4(0.f, 0.f, 0.f, 0.f);
        if (bm + arow < M)
            av = *(const float4*)&A[(long)(bm + arow) * lda + k0 + acol];
        As[acol + 0][arow] = av.x;
        As[acol + 1][arow] = av.y;
        As[acol + 2][arow] = av.z;
        As[acol + 3][arow] = av.w;
        if (TRANSB) {
            #pragma unroll
            for (int j = 0; j < 4; j++) {
                int n = tn0 + 32 * j;
                Bs[tkk][n] = B[(long)(bn + n) * ldb + k0 + tkk];
            }
        } else {
            float4 bv = *(const float4*)&B[(long)(k0 + brow) * ldb + bn + bcol];
            *(float4*)&Bs[brow][bcol] = bv;
        }
        __syncthreads();
        #pragma unroll
        for (int kk = 0; kk < BK; kk++) {
            float4 a0 = *(const float4*)&As[kk][ty * 4];
            float4 a1 = *(const float4*)&As[kk][ty * 4 + 64];
            float4 b0 = *(const float4*)&Bs[kk][tx * 4];
            float4 b1 = *(const float4*)&Bs[kk][tx * 4 + 64];
            float ar[8] = {a0.x, a0.y, a0.z, a0.w, a1.x, a1.y, a1.z, a1.w};
            float br[8] = {b0.x, b0.y, b0.z, b0.w, b1.x, b1.y, b1.z, b1.w};
            #pragma unroll
            for (int i = 0; i < 8; i++)
                #pragma unroll
                for (int j = 0; j < 8; j++)
                    acc[i][j] = fmaf(ar[i], br[j], acc[i][j]);
        }
        __syncthreads();
    }

    #pragma unroll
    for (int i = 0; i < 8; i++) {
        int m = bm + ty * 4 + (i & 3) + (i >> 2) * 64;
        if (m >= M) continue;
        #pragma unroll
        for (int j = 0; j < 8; j++) {
            int n = bn + tx * 4 + (j & 3) + (j >> 2) * 64;
            if (n >= N) continue;
            float v = acc[i][j];
            if (ACT) {
                float xx = v;
                v = 0.5f * xx * (1.0f + tanhf(0.7978845608028654f *
                        (xx + 0.044715f * xx * xx * xx)));
            }
            C[(long)m * ldc + n] = v;
        }
    }
}

// ---------------- launch ----------------
extern "C" void kernel_launch(void* const* d_in, const int* in_sizes, int n_in,
                              void* d_out, int out_size) {
    const int*   ids      = (const int*)  d_in[0];
    const float* embed_w  = (const float*)d_in[1];
    const float* router_w = (const float*)d_in[2];
    const float* w1       = (const float*)d_in[3];
    const float* w2       = (const float*)d_in[4];
    const float* lns      = (const float*)d_in[5];
    float* out = (float*)d_out;

    float *p_xin, *p_mid, *p_eout, *p_hn;
    int   *p_counts;
    cudaGetSymbolAddress((void**)&p_xin,    g_xin);
    cudaGetSymbolAddress((void**)&p_mid,    g_mid);
    cudaGetSymbolAddress((void**)&p_eout,   g_eout);
    cudaGetSymbolAddress((void**)&p_hn,     g_hn);
    cudaGetSymbolAddress((void**)&p_counts, g_counts);

    rope_init_kernel<<<cT, 64>>>();
    embed_gather_kernel<<<(int)(((long)cT * cD + 255) / 256), 256>>>(ids, embed_w);

    for (int hop = 0; hop < cHOPS; hop++) {
        router_logits_kernel<<<cT, 512>>>(router_w + (long)hop * cD * cE);
        token_route_kernel<<<(cT + 255) / 256, 256>>>();
        capacity_kernel<<<cE, 256>>>();
        gather_rope_kernel<<<dim3(cCAP, cE), 256>>>();
        // mid = gelu(xin @ w1[e])   [cnt_e,1024] x [1024,4096]
        sgemm_kernel<0, 1><<<dim3(cDFF / 128, cCAP / 128, cE), 256>>>(
            p_xin, w1, p_mid,
            cCAP, cDFF, cD, cD, cDFF, cDFF,
            (long)cCAP * cD, (long)cD * cDFF, (long)cCAP * cDFF, p_counts);
        // eout = mid @ w2[e]        [cnt_e,4096] x [4096,1024]
        sgemm_kernel<0, 0><<<dim3(cD / 128, cCAP / 128, cE), 256>>>(
            p_mid, w2, p_eout,
            cCAP, cD, cDFF, cDFF, cD, cD,
            (long)cCAP * cDFF, (long)cDFF * cD, (long)cCAP * cD, p_counts);
        combine_kernel<<<cT, 256>>>();
    }

    rmsnorm_kernel<<<cT, 256>>>(lns);
    // logits = hn @ embed_w^T   [2048,1024] x [1024,32000] (B transposed)
    sgemm_kernel<1, 0><<<dim3(cV / 128, cT / 128, 1), 256>>>(
        p_hn, embed_w, out,
        cT, cV, cD, cD, cD, cV,
        0, 0, 0, nullptr);
}

// round 4
// speedup vs baseline: 1.8538x; 1.8538x over previous
#include <cuda_runtime.h>
#include <math.h>
#include <stdint.h>

// ---------------- problem constants ----------------
constexpr int cT   = 2048;
constexpr int cD   = 1024;
constexpr int cV   = 32000;
constexpr int cE   = 16;
constexpr int cK   = 2;
constexpr int cCAP = 512;
constexpr int cDH  = 64;
constexpr int cDFF = 4096;
constexpr int cHOPS= 2;

// ---------------- device scratch ----------------
__device__ float g_h   [cT * cD];
__device__ float g_hn  [cT * cD];
__device__ float g_cos [cT * cDH];
__device__ float g_sin [cT * cDH];
__device__ float g_logits[cT * cE];
__device__ float g_probs [cT * cE];
__device__ unsigned char g_mask[cT * cE];
__device__ int   g_kept_slot[cT * cE];
__device__ int   g_counts[cE];
__device__ int   g_etok[cE * cCAP];
__device__ float g_xin [(long)cE * cCAP * cD];
__device__ float g_mid [(long)cE * cCAP * cDFF];
__device__ float g_eout[(long)cE * cCAP * cD];

// ---------------- small kernels ----------------
__global__ void rope_init_kernel() {
    int t = blockIdx.x;
    int i = threadIdx.x;
    int j = 2 * (i & 31);
    float inv = powf(10000.0f, -(float)j / (float)cDH);
    float fr  = (float)t * inv;
    g_cos[t * cDH + i] = cosf(fr);
    g_sin[t * cDH + i] = sinf(fr);
}

__global__ void embed_gather_kernel(const int* __restrict__ ids,
                                    const float* __restrict__ ew) {
    long idx = (long)blockIdx.x * blockDim.x + threadIdx.x;
    if (idx >= (long)cT * cD) return;
    int t = (int)(idx >> 10);
    int d = (int)(idx & (cD - 1));
    g_h[idx] = ew[(long)ids[t] * cD + d];
}

__global__ void router_logits_kernel(const float* __restrict__ wr) {
    int t    = blockIdx.x;
    int e    = threadIdx.x >> 5;
    int lane = threadIdx.x & 31;
    float s = 0.f;
    const float* hp = &g_h[(long)t * cD];
    for (int d = lane; d < cD; d += 32)
        s += hp[d] * wr[(long)d * cE + e];
    #pragma unroll
    for (int o = 16; o; o >>= 1) s += __shfl_down_sync(0xffffffffu, s, o);
    if (lane == 0) g_logits[t * cE + e] = s;
}

__global__ void token_route_kernel() {
    int t = blockIdx.x * blockDim.x + threadIdx.x;
    if (t >= cT) return;
    float l[cE];
    #pragma unroll
    for (int e = 0; e < cE; e++) l[e] = g_logits[t * cE + e];
    int i1 = 0; float v1 = l[0];
    #pragma unroll
    for (int e = 1; e < cE; e++) if (l[e] > v1) { v1 = l[e]; i1 = e; }
    int i2 = -1; float v2 = -INFINITY;
    #pragma unroll
    for (int e = 0; e < cE; e++) if (e != i1 && l[e] > v2) { v2 = l[e]; i2 = e; }
    float sum = 0.f; float p[cE];
    #pragma unroll
    for (int e = 0; e < cE; e++) { p[e] = expf(l[e] - v1); sum += p[e]; }
    float invs = 1.0f / sum;
    #pragma unroll
    for (int e = 0; e < cE; e++) {
        g_probs[t * cE + e] = p[e] * invs;
        g_mask [t * cE + e] = (e == i1 || e == i2) ? 1 : 0;
        g_kept_slot[t * cE + e] = -1;
    }
    if (t < cE) g_counts[t] = 0;
}

// capacity: compact masked candidates, then exact rank (value desc, index asc)
__global__ void capacity_kernel() {
    int e = blockIdx.x;
    __shared__ int   cnt;
    __shared__ int   idx[cT];
    __shared__ float val[cT];
    if (threadIdx.x == 0) cnt = 0;
    __syncthreads();
    for (int t = threadIdx.x; t < cT; t += blockDim.x) {
        if (g_mask[t * cE + e]) {
            int p = atomicAdd(&cnt, 1);
            idx[p] = t;
            val[p] = g_logits[t * cE + e];
        }
    }
    __syncthreads();
    int n = cnt;
    for (int i = threadIdx.x; i < n; i += blockDim.x) {
        float v = val[i]; int t = idx[i];
        int rank = 0;
        for (int j = 0; j < n; j++) {
            float u = val[j]; int s = idx[j];
            rank += (u > v || (u == v && s < t)) ? 1 : 0;
        }
        if (rank < cCAP) {
            int slot = atomicAdd(&g_counts[e], 1);
            g_etok[e * cCAP + slot] = t;
            g_kept_slot[t * cE + e] = slot;
        }
    }
}

__global__ void gather_rope_kernel() {
    int c = blockIdx.x;
    int e = blockIdx.y;
    if (c >= g_counts[e]) return;
    int t = g_etok[e * cCAP + c];
    __shared__ float x[cD];
    for (int d = threadIdx.x; d < cD; d += blockDim.x) x[d] = g_h[(long)t * cD + d];
    __syncthreads();
    const float* cs = &g_cos[t * cDH];
    const float* sn = &g_sin[t * cDH];
    float* out = &g_xin[((long)(e * cCAP + c)) * cD];
    for (int d = threadIdx.x; d < cD; d += blockDim.x) {
        int i = d & (cDH - 1);
        float r = (i < 32) ? -x[d + 32] : x[d - 32];
        out[d] = x[d] * cs[i] + r * sn[i];
    }
}

__global__ void combine_kernel() {
    int t = blockIdx.x;
    int ne = 0;
    int ks[cK]; float kp[cK]; int ke[cK];
    float rho = 0.f;
    #pragma unroll
    for (int e = 0; e < cE; e++) {
        int s = g_kept_slot[t * cE + e];
        if (s >= 0) {
            float p = g_probs[t * cE + e];
            rho += p;
            if (ne < cK) { ke[ne] = e; ks[ne] = s; kp[ne] = p; ne++; }
        }
    }
    for (int d = threadIdx.x; d < cD; d += blockDim.x) {
        float hv = g_h[(long)t * cD + d];
        float comb = 0.f;
        for (int q = 0; q < ne; q++)
            comb += kp[q] * g_eout[((long)(ke[q] * cCAP + ks[q])) * cD + d];
        g_h[(long)t * cD + d] = hv + comb - rho * hv;
    }
}

__global__ void rmsnorm_kernel(const float* __restrict__ lns) {
    int t = blockIdx.x;
    __shared__ float red[256];
    float s = 0.f;
    for (int d = threadIdx.x; d < cD; d += 256) {
        float v = g_h[(long)t * cD + d];
        s += v * v;
    }
    red[threadIdx.x] = s;
    __syncthreads();
    #pragma unroll
    for (int o = 128; o; o >>= 1) {
        if (threadIdx.x < o) red[threadIdx.x] += red[threadIdx.x + o];
        __syncthreads();
    }
    float inv = rsqrtf(red[0] / (float)cD + 1e-6f);
    for (int d = threadIdx.x; d < cD; d += 256)
        g_hn[(long)t * cD + d] = g_h[(long)t * cD + d] * lns[d] * inv;
}

// ---------------- mma.sync tf32 GEMM ----------------
// C[M,N] = act(A @ B), A[M,K] row-major.
// BLAYOUT=0: B[k*ldb + n]  (w1/w2 natural layout)
// BLAYOUT=1: B[n*ldb + k]  (embed_w for logits)
// NPASS=3: tf32x3 (fp32-class accuracy); NPASS=1: single tf32.
// Tiles: BM=BN=128, BK=32; 8 warps (4 M x 2 N), warp tile 32x64; 3-stage cp.async.

__device__ __forceinline__ uint32_t cvt_tf32(float x) {
    uint32_t u; asm("cvt.rna.tf32.f32 %0, %1;" : "=r"(u) : "f"(x)); return u;
}
__device__ __forceinline__ void split_tf32(float x, uint32_t& hi, uint32_t& lo) {
    hi = cvt_tf32(x);
    lo = cvt_tf32(x - __uint_as_float(hi));
}
__device__ __forceinline__ void mma1688(float& c0, float& c1, float& c2, float& c3,
                                        uint32_t a0, uint32_t a1, uint32_t a2, uint32_t a3,
                                        uint32_t b0, uint32_t b1) {
    asm volatile(
        "mma.sync.aligned.m16n8k8.row.col.f32.tf32.tf32.f32 "
        "{%0,%1,%2,%3}, {%4,%5,%6,%7}, {%8,%9}, {%0,%1,%2,%3};"
        : "+f"(c0), "+f"(c1), "+f"(c2), "+f"(c3)
        : "r"(a0), "r"(a1), "r"(a2), "r"(a3), "r"(b0), "r"(b1));
}
__device__ __forceinline__ void cpa16(uint32_t dst, const void* src, int sz) {
    asm volatile("cp.async.cg.shared.global [%0], [%1], 16, %2;"
                 :: "r"(dst), "l"(src), "r"(sz) : "memory");
}
__device__ __forceinline__ uint32_t s2u(const void* p) {
    uint32_t a;
    asm("{ .reg .u64 t; cvta.to.shared.u64 t, %1; cvt.u32.u64 %0, t; }" : "=r"(a) : "l"(p));
    return a;
}

constexpr int AST  = 36;    // A smem row stride (floats), conflict-free
constexpr int BST0 = 132;   // B smem row stride for BLAYOUT=0
constexpr int A_FLOATS = 128 * AST;          // 4608
constexpr int B_FLOATS = 128 * AST;          // max(32*132=4224, 128*36=4608)
constexpr int STG_FLOATS = A_FLOATS + B_FLOATS;  // 9216
constexpr int GEMM_SMEM  = 3 * STG_FLOATS * 4;   // 110592 B

template<int BLAYOUT, int NPASS, int ACT>
__global__ void __launch_bounds__(256, 1)
mma_gemm(const float* __restrict__ Ag, const float* __restrict__ Bg, float* __restrict__ Cg,
         int Kd, int lda, int ldb, int ldc,
         long sA, long sB, long sC, const int* __restrict__ Mvec, int Mfix)
{
    extern __shared__ float sm[];
    int e  = blockIdx.z;
    int Me = Mvec ? Mvec[e] : Mfix;
    int bm = blockIdx.y * 128;
    if (bm >= Me) return;
    int bn = blockIdx.x * 128;
    const float* A = Ag + (long)e * sA;
    const float* B = Bg + (long)e * sB;
    float*       C = Cg + (long)e * sC;

    int tid  = threadIdx.x;
    int wid  = tid >> 5, lane = tid & 31;
    int g    = lane >> 2, tg = lane & 3;
    int wm   = (wid & 3) * 32;      // warp row offset in tile
    int wn   = (wid >> 2) * 64;     // warp col offset in tile

    uint32_t smu = s2u(sm);

    // stage loader
    auto load_stage = [&](int s, int k0) {
        uint32_t sa = smu + (s * STG_FLOATS) * 4;
        uint32_t sb = sa + A_FLOATS * 4;
        #pragma unroll
        for (int j = 0; j < 4; j++) {           // A: 128 rows x 32 k
            int q   = tid + 256 * j;
            int row = q >> 3, c4 = q & 7;
            int grow = bm + row;
            int ok   = grow < Me;
            const float* src = A + (long)(ok ? grow : 0) * lda + k0 + c4 * 4;
            cpa16(sa + (row * AST + c4 * 4) * 4, src, ok ? 16 : 0);
        }
        if (BLAYOUT == 0) {
            #pragma unroll
            for (int j = 0; j < 4; j++) {       // B: 32 k-rows x 128 n
                int q = tid + 256 * j;
                int kr = q >> 5, n4 = q & 31;
                const float* src = B + (long)(k0 + kr) * ldb + bn + n4 * 4;
                cpa16(sb + (kr * BST0 + n4 * 4) * 4, src, 16);
            }
        } else {
            #pragma unroll
            for (int j = 0; j < 4; j++) {       // B: 128 n-rows x 32 k
                int q = tid + 256 * j;
                int row = q >> 3, c4 = q & 7;
                const float* src = B + (long)(bn + row) * ldb + k0 + c4 * 4;
                cpa16(sb + (row * AST + c4 * 4) * 4, src, 16);
            }
        }
        asm volatile("cp.async.commit_group;" ::: "memory");
    };

    float c[2][8][4];
    #pragma unroll
    for (int mi = 0; mi < 2; mi++)
        #pragma unroll
        for (int ni = 0; ni < 8; ni++)
            #pragma unroll
            for (int q = 0; q < 4; q++) c[mi][ni][q] = 0.f;

    int nK = Kd >> 5;
    load_stage(0, 0);
    load_stage(1, 32);

    for (int i = 0; i < nK; i++) {
        asm volatile("cp.async.wait_group 1;" ::: "memory");
        __syncthreads();
        if (i + 2 < nK) load_stage((i + 2) % 3, (i + 2) * 32);
        else asm volatile("cp.async.commit_group;" ::: "memory");

        const float* As = sm + (i % 3) * STG_FLOATS;
        const float* Bs = As + A_FLOATS;

        #pragma unroll
        for (int ks = 0; ks < 4; ks++) {
            int kb = ks * 8;
            uint32_t ahi[2][4], alo[2][4];
            #pragma unroll
            for (int mi = 0; mi < 2; mi++) {
                int r0 = wm + mi * 16 + g;
                float a0 = As[r0 * AST + kb + tg];
                float a1 = As[(r0 + 8) * AST + kb + tg];
                float a2 = As[r0 * AST + kb + tg + 4];
                float a3 = As[(r0 + 8) * AST + kb + tg + 4];
                if (NPASS == 3) {
                    split_tf32(a0, ahi[mi][0], alo[mi][0]);
                    split_tf32(a1, ahi[mi][1], alo[mi][1]);
                    split_tf32(a2, ahi[mi][2], alo[mi][2]);
                    split_tf32(a3, ahi[mi][3], alo[mi][3]);
                } else {
                    ahi[mi][0] = cvt_tf32(a0); ahi[mi][1] = cvt_tf32(a1);
                    ahi[mi][2] = cvt_tf32(a2); ahi[mi][3] = cvt_tf32(a3);
                }
            }
            uint32_t bhi[8][2], blo[8][2];
            #pragma unroll
            for (int ni = 0; ni < 8; ni++) {
                float b0, b1;
                if (BLAYOUT == 0) {
                    int n = wn + ni * 8 + g;
                    b0 = Bs[(kb + tg) * BST0 + n];
                    b1 = Bs[(kb + tg + 4) * BST0 + n];
                } else {
                    int n = wn + ni * 8 + g;
                    b0 = Bs[n * AST + kb + tg];
                    b1 = Bs[n * AST + kb + tg + 4];
                }
                if (NPASS == 3) {
                    split_tf32(b0, bhi[ni][0], blo[ni][0]);
                    split_tf32(b1, bhi[ni][1], blo[ni][1]);
                } else {
                    bhi[ni][0] = cvt_tf32(b0); bhi[ni][1] = cvt_tf32(b1);
                }
            }
            #pragma unroll
            for (int mi = 0; mi < 2; mi++)
                #pragma unroll
                for (int ni = 0; ni < 8; ni++)
                    mma1688(c[mi][ni][0], c[mi][ni][1], c[mi][ni][2], c[mi][ni][3],
                            ahi[mi][0], ahi[mi][1], ahi[mi][2], ahi[mi][3],
                            bhi[ni][0], bhi[ni][1]);
            if (NPASS == 3) {
                #pragma unroll
                for (int mi = 0; mi < 2; mi++)
                    #pragma unroll
                    for (int ni = 0; ni < 8; ni++)
                        mma1688(c[mi][ni][0], c[mi][ni][1], c[mi][ni][2], c[mi][ni][3],
                                ahi[mi][0], ahi[mi][1], ahi[mi][2], ahi[mi][3],
                                blo[ni][0], blo[ni][1]);
                #pragma unroll
                for (int mi = 0; mi < 2; mi++)
                    #pragma unroll
                    for (int ni = 0; ni < 8; ni++)
                        mma1688(c[mi][ni][0], c[mi][ni][1], c[mi][ni][2], c[mi][ni][3],
                                alo[mi][0], alo[mi][1], alo[mi][2], alo[mi][3],
                                bhi[ni][0], bhi[ni][1]);
            }
        }
        __syncthreads();
    }

    // epilogue
    #pragma unroll
    for (int mi = 0; mi < 2; mi++) {
        int r0 = bm + wm + mi * 16 + g;
        #pragma unroll
        for (int ni = 0; ni < 8; ni++) {
            int col = bn + wn + ni * 8 + tg * 2;
            float v0 = c[mi][ni][0], v1 = c[mi][ni][1];
            float v2 = c[mi][ni][2], v3 = c[mi][ni][3];
            if (ACT) {
                v0 = 0.5f * v0 * (1.0f + tanhf(0.7978845608028654f * (v0 + 0.044715f * v0 * v0 * v0)));
                v1 = 0.5f * v1 * (1.0f + tanhf(0.7978845608028654f * (v1 + 0.044715f * v1 * v1 * v1)));
                v2 = 0.5f * v2 * (1.0f + tanhf(0.7978845608028654f * (v2 + 0.044715f * v2 * v2 * v2)));
                v3 = 0.5f * v3 * (1.0f + tanhf(0.7978845608028654f * (v3 + 0.044715f * v3 * v3 * v3)));
            }
            if (r0 < Me)     *(float2*)&C[(long)r0 * ldc + col]       = make_float2(v0, v1);
            if (r0 + 8 < Me) *(float2*)&C[(long)(r0 + 8) * ldc + col] = make_float2(v2, v3);
        }
    }
}

// ---------------- launch ----------------
extern "C" void kernel_launch(void* const* d_in, const int* in_sizes, int n_in,
                              void* d_out, int out_size) {
    const int*   ids      = (const int*)  d_in[0];
    const float* embed_w  = (const float*)d_in[1];
    const float* router_w = (const float*)d_in[2];
    const float* w1       = (const float*)d_in[3];
    const float* w2       = (const float*)d_in[4];
    const float* lns      = (const float*)d_in[5];
    float* out = (float*)d_out;

    float *p_xin, *p_mid, *p_eout, *p_hn;
    int   *p_counts;
    cudaGetSymbolAddress((void**)&p_xin,    g_xin);
    cudaGetSymbolAddress((void**)&p_mid,    g_mid);
    cudaGetSymbolAddress((void**)&p_eout,   g_eout);
    cudaGetSymbolAddress((void**)&p_hn,     g_hn);
    cudaGetSymbolAddress((void**)&p_counts, g_counts);

    cudaFuncSetAttribute(mma_gemm<0,3,1>, cudaFuncAttributeMaxDynamicSharedMemorySize, GEMM_SMEM);
    cudaFuncSetAttribute(mma_gemm<0,3,0>, cudaFuncAttributeMaxDynamicSharedMemorySize, GEMM_SMEM);
    cudaFuncSetAttribute(mma_gemm<1,1,0>, cudaFuncAttributeMaxDynamicSharedMemorySize, GEMM_SMEM);

    rope_init_kernel<<<cT, 64>>>();
    embed_gather_kernel<<<(int)(((long)cT * cD + 255) / 256), 256>>>(ids, embed_w);

    for (int hop = 0; hop < cHOPS; hop++) {
        router_logits_kernel<<<cT, 512>>>(router_w + (long)hop * cD * cE);
        token_route_kernel<<<(cT + 255) / 256, 256>>>();
        capacity_kernel<<<cE, 256>>>();
        gather_rope_kernel<<<dim3(cCAP, cE), 256>>>();
        // mid = gelu(xin @ w1[e]):  M=cnt_e, N=4096, K=1024, B natural [K,N]
        mma_gemm<0,3,1><<<dim3(cDFF / 128, cCAP / 128, cE), 256, GEMM_SMEM>>>(
            p_xin, w1, p_mid, cD, cD, cDFF, cDFF,
            (long)cCAP * cD, (long)cD * cDFF, (long)cCAP * cDFF, p_counts, 0);
        // eout = mid @ w2[e]:  M=cnt_e, N=1024, K=4096, B natural [K,N]
        mma_gemm<0,3,0><<<dim3(cD / 128, cCAP / 128, cE), 256, GEMM_SMEM>>>(
            p_mid, w2, p_eout, cDFF, cDFF, cD, cD,
            (long)cCAP * cDFF, (long)cDFF * cD, (long)cCAP * cD, p_counts, 0);
        combine_kernel<<<cT, 256>>>();
    }

    rmsnorm_kernel<<<cT, 256>>>(lns);
    // logits = hn @ embed_w^T: M=2048, N=32000, K=1024, B = embed_w [N,K]
    mma_gemm<1,1,0><<<dim3(cV / 128, cT / 128, 1), 256, GEMM_SMEM>>>(
        p_hn, embed_w, out, cD, cD, cD, cV,
        0, 0, 0, nullptr, cT);
}

// round 5
// speedup vs baseline: 2.4086x; 1.2992x over previous
#include <cuda_runtime.h>
#include <cuda_fp16.h>
#include <math.h>
#include <stdint.h>

// ---------------- problem constants ----------------
constexpr int cT   = 2048;
constexpr int cD   = 1024;
constexpr int cV   = 32000;
constexpr int cE   = 16;
constexpr int cK   = 2;
constexpr int cCAP = 512;
constexpr int cDH  = 64;
constexpr int cDFF = 4096;
constexpr int cHOPS= 2;

// ---------------- device scratch ----------------
__device__ float g_h   [cT * cD];
__device__ float g_hn  [cT * cD];
__device__ float g_cos [cT * cDH];
__device__ float g_sin [cT * cDH];
__device__ float g_logits[cT * cE];
__device__ float g_probs [cT * cE];
__device__ unsigned char g_mask[cT * cE];
__device__ int   g_kept_slot[cT * cE];
__device__ int   g_counts[cE];
__device__ int   g_etok[cE * cCAP];
__device__ float g_xin [(long)cE * cCAP * cD];
__device__ float g_mid [(long)cE * cCAP * cDFF];
__device__ float g_eout[(long)cE * cCAP * cD];

// ---------------- small kernels ----------------
__global__ void rope_init_kernel() {
    int t = blockIdx.x;
    int i = threadIdx.x;
    int j = 2 * (i & 31);
    float inv = powf(10000.0f, -(float)j / (float)cDH);
    float fr  = (float)t * inv;
    g_cos[t * cDH + i] = cosf(fr);
    g_sin[t * cDH + i] = sinf(fr);
}

__global__ void embed_gather_kernel(const int* __restrict__ ids,
                                    const float* __restrict__ ew) {
    long idx = (long)blockIdx.x * blockDim.x + threadIdx.x;
    if (idx >= (long)cT * cD) return;
    int t = (int)(idx >> 10);
    int d = (int)(idx & (cD - 1));
    g_h[idx] = ew[(long)ids[t] * cD + d];
}

__global__ void router_logits_kernel(const float* __restrict__ wr) {
    int t    = blockIdx.x;
    int e    = threadIdx.x >> 5;
    int lane = threadIdx.x & 31;
    float s = 0.f;
    const float* hp = &g_h[(long)t * cD];
    for (int d = lane; d < cD; d += 32)
        s += hp[d] * wr[(long)d * cE + e];
    #pragma unroll
    for (int o = 16; o; o >>= 1) s += __shfl_down_sync(0xffffffffu, s, o);
    if (lane == 0) g_logits[t * cE + e] = s;
}

__global__ void token_route_kernel() {
    int t = blockIdx.x * blockDim.x + threadIdx.x;
    if (t >= cT) return;
    float l[cE];
    #pragma unroll
    for (int e = 0; e < cE; e++) l[e] = g_logits[t * cE + e];
    int i1 = 0; float v1 = l[0];
    #pragma unroll
    for (int e = 1; e < cE; e++) if (l[e] > v1) { v1 = l[e]; i1 = e; }
    int i2 = -1; float v2 = -INFINITY;
    #pragma unroll
    for (int e = 0; e < cE; e++) if (e != i1 && l[e] > v2) { v2 = l[e]; i2 = e; }
    float sum = 0.f; float p[cE];
    #pragma unroll
    for (int e = 0; e < cE; e++) { p[e] = expf(l[e] - v1); sum += p[e]; }
    float invs = 1.0f / sum;
    #pragma unroll
    for (int e = 0; e < cE; e++) {
        g_probs[t * cE + e] = p[e] * invs;
        g_mask [t * cE + e] = (e == i1 || e == i2) ? 1 : 0;
        g_kept_slot[t * cE + e] = -1;
    }
    if (t < cE) g_counts[t] = 0;
}

__global__ void capacity_kernel() {
    int e = blockIdx.x;
    __shared__ int   cnt;
    __shared__ int   idx[cT];
    __shared__ float val[cT];
    if (threadIdx.x == 0) cnt = 0;
    __syncthreads();
    for (int t = threadIdx.x; t < cT; t += blockDim.x) {
        if (g_mask[t * cE + e]) {
            int p = atomicAdd(&cnt, 1);
            idx[p] = t;
            val[p] = g_logits[t * cE + e];
        }
    }
    __syncthreads();
    int n = cnt;
    for (int i = threadIdx.x; i < n; i += blockDim.x) {
        float v = val[i]; int t = idx[i];
        int rank = 0;
        for (int j = 0; j < n; j++) {
            float u = val[j]; int s = idx[j];
            rank += (u > v || (u == v && s < t)) ? 1 : 0;
        }
        if (rank < cCAP) {
            int slot = atomicAdd(&g_counts[e], 1);
            g_etok[e * cCAP + slot] = t;
            g_kept_slot[t * cE + e] = slot;
        }
    }
}

__global__ void gather_rope_kernel() {
    int c = blockIdx.x;
    int e = blockIdx.y;
    if (c >= g_counts[e]) return;
    int t = g_etok[e * cCAP + c];
    __shared__ float x[cD];
    for (int d = threadIdx.x; d < cD; d += blockDim.x) x[d] = g_h[(long)t * cD + d];
    __syncthreads();
    const float* cs = &g_cos[t * cDH];
    const float* sn = &g_sin[t * cDH];
    float* out = &g_xin[((long)(e * cCAP + c)) * cD];
    for (int d = threadIdx.x; d < cD; d += blockDim.x) {
        int i = d & (cDH - 1);
        float r = (i < 32) ? -x[d + 32] : x[d - 32];
        out[d] = x[d] * cs[i] + r * sn[i];
    }
}

__global__ void combine_kernel() {
    int t = blockIdx.x;
    int ne = 0;
    int ks[cK]; float kp[cK]; int ke[cK];
    float rho = 0.f;
    #pragma unroll
    for (int e = 0; e < cE; e++) {
        int s = g_kept_slot[t * cE + e];
        if (s >= 0) {
            float p = g_probs[t * cE + e];
            rho += p;
            if (ne < cK) { ke[ne] = e; ks[ne] = s; kp[ne] = p; ne++; }
        }
    }
    for (int d = threadIdx.x; d < cD; d += blockDim.x) {
        float hv = g_h[(long)t * cD + d];
        float comb = 0.f;
        for (int q = 0; q < ne; q++)
            comb += kp[q] * g_eout[((long)(ke[q] * cCAP + ks[q])) * cD + d];
        g_h[(long)t * cD + d] = hv + comb - rho * hv;
    }
}

__global__ void rmsnorm_kernel(const float* __restrict__ lns) {
    int t = blockIdx.x;
    __shared__ float red[256];
    float s = 0.f;
    for (int d = threadIdx.x; d < cD; d += 256) {
        float v = g_h[(long)t * cD + d];
        s += v * v;
    }
    red[threadIdx.x] = s;
    __syncthreads();
    #pragma unroll
    for (int o = 128; o; o >>= 1) {
        if (threadIdx.x < o) red[threadIdx.x] += red[threadIdx.x + o];
        __syncthreads();
    }
    float inv = rsqrtf(red[0] / (float)cD + 1e-6f);
    for (int d = threadIdx.x; d < cD; d += 256)
        g_hn[(long)t * cD + d] = g_h[(long)t * cD + d] * lns[d] * inv;
}

// ---------------- common device helpers ----------------
__device__ __forceinline__ uint32_t s2u(const void* p) {
    uint32_t a;
    asm("{ .reg .u64 t; cvta.to.shared.u64 t, %1; cvt.u32.u64 %0, t; }" : "=r"(a) : "l"(p));
    return a;
}
__device__ __forceinline__ uint32_t cvt_tf32(float x) {
    uint32_t u; asm("cvt.rna.tf32.f32 %0, %1;" : "=r"(u) : "f"(x)); return u;
}
__device__ __forceinline__ void mma1688(float& c0, float& c1, float& c2, float& c3,
                                        uint32_t a0, uint32_t a1, uint32_t a2, uint32_t a3,
                                        uint32_t b0, uint32_t b1) {
    asm volatile(
        "mma.sync.aligned.m16n8k8.row.col.f32.tf32.tf32.f32 "
        "{%0,%1,%2,%3}, {%4,%5,%6,%7}, {%8,%9}, {%0,%1,%2,%3};"
        : "+f"(c0), "+f"(c1), "+f"(c2), "+f"(c3)
        : "r"(a0), "r"(a1), "r"(a2), "r"(a3), "r"(b0), "r"(b1));
}
__device__ __forceinline__ void mma16816(float& c0, float& c1, float& c2, float& c3,
                                         uint32_t a0, uint32_t a1, uint32_t a2, uint32_t a3,
                                         uint32_t b0, uint32_t b1) {
    asm volatile(
        "mma.sync.aligned.m16n8k16.row.col.f32.f16.f16.f32 "
        "{%0,%1,%2,%3}, {%4,%5,%6,%7}, {%8,%9}, {%0,%1,%2,%3};"
        : "+f"(c0), "+f"(c1), "+f"(c2), "+f"(c3)
        : "r"(a0), "r"(a1), "r"(a2), "r"(a3), "r"(b0), "r"(b1));
}
__device__ __forceinline__ void cpa16(uint32_t dst, const void* src, int sz) {
    asm volatile("cp.async.cg.shared.global [%0], [%1], 16, %2;"
                 :: "r"(dst), "l"(src), "r"(sz) : "memory");
}
__device__ __forceinline__ void split_pair(float x0, float x1, uint32_t& hi, uint32_t& lo) {
    __half h0 = __float2half_rn(x0), h1 = __float2half_rn(x1);
    __half l0 = __float2half_rn(x0 - __half2float(h0));
    __half l1 = __float2half_rn(x1 - __half2float(h1));
    __half2 hv = __halves2half2(h0, h1), lv = __halves2half2(l0, l1);
    hi = *(uint32_t*)&hv; lo = *(uint32_t*)&lv;
}
__device__ __forceinline__ float gelu1(float x) {
    return 0.5f * x * (1.0f + tanhf(0.7978845608028654f * (x + 0.044715f * x * x * x)));
}

// ---------------- fp16x2 GEMM for experts ----------------
// C[M,N] = act(A @ B), A[M,K] row-major, B[K,N] row-major (natural w1/w2 layout).
// BM=BN=128, BK=32, 8 warps (4M x 2N), warp tile 32x64, 2-stage smem,
// register-prefetch pipeline, operands pre-split hi/lo fp16 in the loader.
constexpr int HSTR  = 20;                   // b32 (half2) row stride, conflict-free
constexpr int HSEG  = 128 * HSTR;           // 2560 b32 per matrix per stage
constexpr int HSTAGE= 4 * HSEG;             // Ahi, Alo, Bhi, Blo
constexpr int HGEMM_SMEM = 2 * HSTAGE * 4;  // 81920 B

template<int ACT>
__global__ void __launch_bounds__(256, 1)
hgemm_x2(const float* __restrict__ Ag, const float* __restrict__ Bg, float* __restrict__ Cg,
         int Kd, int lda, int ldb, int ldc,
         long sA, long sB, long sC, const int* __restrict__ Mvec)
{
    extern __shared__ uint32_t sh[];
    int e  = blockIdx.z;
    int Me = Mvec[e];
    int bm = blockIdx.y * 128;
    if (bm >= Me) return;
    int bn = blockIdx.x * 128;
    const float* A = Ag + (long)e * sA;
    const float* B = Bg + (long)e * sB;
    float*       C = Cg + (long)e * sC;

    int tid = threadIdx.x;
    int wid = tid >> 5, lane = tid & 31;
    int g   = lane >> 2, tg = lane & 3;
    int wm  = (wid & 3) * 32;
    int wn  = (wid >> 2) * 64;

    // prefetch registers
    float4 pA[4], pB0[2], pB1[2];

    auto load_regs = [&](int k0) {
        #pragma unroll
        for (int j = 0; j < 4; j++) {
            int q = tid + 256 * j;
            int row = q >> 3, f4 = q & 7;
            pA[j] = *(const float4*)(A + (long)(bm + row) * lda + k0 + f4 * 4);
        }
        #pragma unroll
        for (int j = 0; j < 2; j++) {
            int q  = tid + 256 * j;
            int kp = q & 15, n4 = q >> 4;           // n4 in 0..31
            pB0[j] = *(const float4*)(B + (long)(k0 + 2 * kp) * ldb + bn + n4 * 4);
            pB1[j] = *(const float4*)(B + (long)(k0 + 2 * kp + 1) * ldb + bn + n4 * 4);
        }
    };
    auto store_stage = [&](int s) {
        uint32_t* Ahi = sh + s * HSTAGE;
        uint32_t* Alo = Ahi + HSEG;
        uint32_t* Bhi = Alo + HSEG;
        uint32_t* Blo = Bhi + HSEG;
        #pragma unroll
        for (int j = 0; j < 4; j++) {
            int q = tid + 256 * j;
            int row = q >> 3, f4 = q & 7;
            uint32_t h0, l0, h1, l1;
            split_pair(pA[j].x, pA[j].y, h0, l0);
            split_pair(pA[j].z, pA[j].w, h1, l1);
            int o = row * HSTR + f4 * 2;
            Ahi[o] = h0; Ahi[o + 1] = h1;
            Alo[o] = l0; Alo[o + 1] = l1;
        }
        #pragma unroll
        for (int j = 0; j < 2; j++) {
            int q  = tid + 256 * j;
            int kp = q & 15, n4 = q >> 4;
            const float* f0 = (const float*)&pB0[j];
            const float* f1 = (const float*)&pB1[j];
            #pragma unroll
            for (int i = 0; i < 4; i++) {
                uint32_t hv, lv;
                split_pair(f0[i], f1[i], hv, lv);
                int o = (n4 * 4 + i) * HSTR + kp;
                Bhi[o] = hv;
                Blo[o] = lv;
            }
        }
    };

    float c[2][8][4];
    #pragma unroll
    for (int mi = 0; mi < 2; mi++)
        #pragma unroll
        for (int ni = 0; ni < 8; ni++)
            #pragma unroll
            for (int q = 0; q < 4; q++) c[mi][ni][q] = 0.f;

    int nK = Kd >> 5;
    load_regs(0);
    store_stage(0);
    __syncthreads();

    for (int i = 0; i < nK; i++) {
        if (i + 1 < nK) load_regs((i + 1) * 32);

        const uint32_t* Ahi = sh + (i & 1) * HSTAGE;
        const uint32_t* Alo = Ahi + HSEG;
        const uint32_t* Bhi = Alo + HSEG;
        const uint32_t* Blo = Bhi + HSEG;

        #pragma unroll
        for (int ks = 0; ks < 2; ks++) {
            int ko = ks * 8;
            uint32_t ah[2][4], al[2][4];
            #pragma unroll
            for (int mi = 0; mi < 2; mi++) {
                int r0 = wm + mi * 16 + g;
                int o0 = r0 * HSTR + ko + tg;
                int o1 = (r0 + 8) * HSTR + ko + tg;
                ah[mi][0] = Ahi[o0];     ah[mi][1] = Ahi[o1];
                ah[mi][2] = Ahi[o0 + 4]; ah[mi][3] = Ahi[o1 + 4];
                al[mi][0] = Alo[o0];     al[mi][1] = Alo[o1];
                al[mi][2] = Alo[o0 + 4]; al[mi][3] = Alo[o1 + 4];
            }
            uint32_t bh[8][2], bl[8][2];
            #pragma unroll
            for (int ni = 0; ni < 8; ni++) {
                int n = wn + ni * 8 + g;
                int o = n * HSTR + ko + tg;
                bh[ni][0] = Bhi[o]; bh[ni][1] = Bhi[o + 4];
                bl[ni][0] = Blo[o]; bl[ni][1] = Blo[o + 4];
            }
            #pragma unroll
            for (int mi = 0; mi < 2; mi++)
                #pragma unroll
                for (int ni = 0; ni < 8; ni++)
                    mma16816(c[mi][ni][0], c[mi][ni][1], c[mi][ni][2], c[mi][ni][3],
                             ah[mi][0], ah[mi][1], ah[mi][2], ah[mi][3],
                             bh[ni][0], bh[ni][1]);
            #pragma unroll
            for (int mi = 0; mi < 2; mi++)
                #pragma unroll
                for (int ni = 0; ni < 8; ni++)
                    mma16816(c[mi][ni][0], c[mi][ni][1], c[mi][ni][2], c[mi][ni][3],
                             ah[mi][0], ah[mi][1], ah[mi][2], ah[mi][3],
                             bl[ni][0], bl[ni][1]);
            #pragma unroll
            for (int mi = 0; mi < 2; mi++)
                #pragma unroll
                for (int ni = 0; ni < 8; ni++)
                    mma16816(c[mi][ni][0], c[mi][ni][1], c[mi][ni][2], c[mi][ni][3],
                             al[mi][0], al[mi][1], al[mi][2], al[mi][3],
                             bh[ni][0], bh[ni][1]);
        }
        if (i + 1 < nK) store_stage((i + 1) & 1);
        __syncthreads();
    }

    #pragma unroll
    for (int mi = 0; mi < 2; mi++) {
        int r0 = bm + wm + mi * 16 + g;
        #pragma unroll
        for (int ni = 0; ni < 8; ni++) {
            int col = bn + wn + ni * 8 + tg * 2;
            float v0 = c[mi][ni][0], v1 = c[mi][ni][1];
            float v2 = c[mi][ni][2], v3 = c[mi][ni][3];
            if (ACT) { v0 = gelu1(v0); v1 = gelu1(v1); v2 = gelu1(v2); v3 = gelu1(v3); }
            if (r0 < Me)     *(float2*)&C[(long)r0 * ldc + col]       = make_float2(v0, v1);
            if (r0 + 8 < Me) *(float2*)&C[(long)(r0 + 8) * ldc + col] = make_float2(v2, v3);
        }
    }
}

// ---------------- tf32 single-pass GEMM for logits ----------------
// C = A @ B^T, B[n*ldb + k]; BM=BN=128, BK=32, 3-stage cp.async.
constexpr int AST  = 36;
constexpr int A_FLOATS = 128 * AST;
constexpr int STG_FLOATS = 2 * A_FLOATS;
constexpr int TGEMM_SMEM = 3 * STG_FLOATS * 4;

__global__ void __launch_bounds__(256, 1)
tgemm_logits(const float* __restrict__ A, const float* __restrict__ B, float* __restrict__ C,
             int Kd, int lda, int ldb, int ldc, int M)
{
    extern __shared__ float sm[];
    int bm = blockIdx.y * 128;
    int bn = blockIdx.x * 128;

    int tid  = threadIdx.x;
    int wid  = tid >> 5, lane = tid & 31;
    int g    = lane >> 2, tg = lane & 3;
    int wm   = (wid & 3) * 32;
    int wn   = (wid >> 2) * 64;

    uint32_t smu = s2u(sm);

    auto load_stage = [&](int s, int k0) {
        uint32_t sa = smu + (s * STG_FLOATS) * 4;
        uint32_t sb = sa + A_FLOATS * 4;
        #pragma unroll
        for (int j = 0; j < 4; j++) {
            int q = tid + 256 * j;
            int row = q >> 3, c4 = q & 7;
            cpa16(sa + (row * AST + c4 * 4) * 4, A + (long)(bm + row) * lda + k0 + c4 * 4, 16);
        }
        #pragma unroll
        for (int j = 0; j < 4; j++) {
            int q = tid + 256 * j;
            int row = q >> 3, c4 = q & 7;
            cpa16(sb + (row * AST + c4 * 4) * 4, B + (long)(bn + row) * ldb + k0 + c4 * 4, 16);
        }
        asm volatile("cp.async.commit_group;" ::: "memory");
    };

    float c[2][8][4];
    #pragma unroll
    for (int mi = 0; mi < 2; mi++)
        #pragma unroll
        for (int ni = 0; ni < 8; ni++)
            #pragma unroll
            for (int q = 0; q < 4; q++) c[mi][ni][q] = 0.f;

    int nK = Kd >> 5;
    load_stage(0, 0);
    load_stage(1, 32);

    for (int i = 0; i < nK; i++) {
        asm volatile("cp.async.wait_group 1;" ::: "memory");
        __syncthreads();
        if (i + 2 < nK) load_stage((i + 2) % 3, (i + 2) * 32);
        else asm volatile("cp.async.commit_group;" ::: "memory");

        const float* As = sm + (i % 3) * STG_FLOATS;
        const float* Bs = As + A_FLOATS;

        #pragma unroll
        for (int ks = 0; ks < 4; ks++) {
            int kb = ks * 8;
            uint32_t a[2][4], b[8][2];
            #pragma unroll
            for (int mi = 0; mi < 2; mi++) {
                int r0 = wm + mi * 16 + g;
                a[mi][0] = cvt_tf32(As[r0 * AST + kb + tg]);
                a[mi][1] = cvt_tf32(As[(r0 + 8) * AST + kb + tg]);
                a[mi][2] = cvt_tf32(As[r0 * AST + kb + tg + 4]);
                a[mi][3] = cvt_tf32(As[(r0 + 8) * AST + kb + tg + 4]);
            }
            #pragma unroll
            for (int ni = 0; ni < 8; ni++) {
                int n = wn + ni * 8 + g;
                b[ni][0] = cvt_tf32(Bs[n * AST + kb + tg]);
                b[ni][1] = cvt_tf32(Bs[n * AST + kb + tg + 4]);
            }
            #pragma unroll
            for (int mi = 0; mi < 2; mi++)
                #pragma unroll
                for (int ni = 0; ni < 8; ni++)
                    mma1688(c[mi][ni][0], c[mi][ni][1], c[mi][ni][2], c[mi][ni][3],
                            a[mi][0], a[mi][1], a[mi][2], a[mi][3],
                            b[ni][0], b[ni][1]);
        }
        __syncthreads();
    }

    #pragma unroll
    for (int mi = 0; mi < 2; mi++) {
        int r0 = bm + wm + mi * 16 + g;
        #pragma unroll
        for (int ni = 0; ni < 8; ni++) {
            int col = bn + wn + ni * 8 + tg * 2;
            *(float2*)&C[(long)r0 * ldc + col]       = make_float2(c[mi][ni][0], c[mi][ni][1]);
            *(float2*)&C[(long)(r0 + 8) * ldc + col] = make_float2(c[mi][ni][2], c[mi][ni][3]);
        }
    }
}

// ---------------- launch ----------------
extern "C" void kernel_launch(void* const* d_in, const int* in_sizes, int n_in,
                              void* d_out, int out_size) {
    const int*   ids      = (const int*)  d_in[0];
    const float* embed_w  = (const float*)d_in[1];
    const float* router_w = (const float*)d_in[2];
    const float* w1       = (const float*)d_in[3];
    const float* w2       = (const float*)d_in[4];
    const float* lns      = (const float*)d_in[5];
    float* out = (float*)d_out;

    float *p_xin, *p_mid, *p_eout, *p_hn;
    int   *p_counts;
    cudaGetSymbolAddress((void**)&p_xin,    g_xin);
    cudaGetSymbolAddress((void**)&p_mid,    g_mid);
    cudaGetSymbolAddress((void**)&p_eout,   g_eout);
    cudaGetSymbolAddress((void**)&p_hn,     g_hn);
    cudaGetSymbolAddress((void**)&p_counts, g_counts);

    cudaFuncSetAttribute(hgemm_x2<1>, cudaFuncAttributeMaxDynamicSharedMemorySize, HGEMM_SMEM);
    cudaFuncSetAttribute(hgemm_x2<0>, cudaFuncAttributeMaxDynamicSharedMemorySize, HGEMM_SMEM);
    cudaFuncSetAttribute(tgemm_logits, cudaFuncAttributeMaxDynamicSharedMemorySize, TGEMM_SMEM);

    rope_init_kernel<<<cT, 64>>>();
    embed_gather_kernel<<<(int)(((long)cT * cD + 255) / 256), 256>>>(ids, embed_w);

    for (int hop = 0; hop < cHOPS; hop++) {
        router_logits_kernel<<<cT, 512>>>(router_w + (long)hop * cD * cE);
        token_route_kernel<<<(cT + 255) / 256, 256>>>();
        capacity_kernel<<<cE, 256>>>();
        gather_rope_kernel<<<dim3(cCAP, cE), 256>>>();
        // mid = gelu(xin @ w1[e]):  M=cnt_e, N=4096, K=1024
        hgemm_x2<1><<<dim3(cDFF / 128, cCAP / 128, cE), 256, HGEMM_SMEM>>>(
            p_xin, w1, p_mid, cD, cD, cDFF, cDFF,
            (long)cCAP * cD, (long)cD * cDFF, (long)cCAP * cDFF, p_counts);
        // eout = mid @ w2[e]:  M=cnt_e, N=1024, K=4096
        hgemm_x2<0><<<dim3(cD / 128, cCAP / 128, cE), 256, HGEMM_SMEM>>>(
            p_mid, w2, p_eout, cDFF, cDFF, cD, cD,
            (long)cCAP * cDFF, (long)cDFF * cD, (long)cCAP * cD, p_counts);
        combine_kernel<<<cT, 256>>>();
    }

    rmsnorm_kernel<<<cT, 256>>>(lns);
    // logits = hn @ embed_w^T: M=2048, N=32000, K=1024
    tgemm_logits<<<dim3(cV / 128, cT / 128, 1), 256, TGEMM_SMEM>>>(
        p_hn, embed_w, out, cD, cD, cD, cV, cT);
}

// round 6
// speedup vs baseline: 2.6436x; 1.0976x over previous
#include <cuda_runtime.h>
#include <cuda_fp16.h>
#include <math.h>
#include <stdint.h>

// ---------------- problem constants ----------------
constexpr int cT   = 2048;
constexpr int cD   = 1024;
constexpr int cV   = 32000;
constexpr int cE   = 16;
constexpr int cK   = 2;
constexpr int cCAP = 512;
constexpr int cDH  = 64;
constexpr int cDFF = 4096;
constexpr int cHOPS= 2;

// ---------------- device scratch ----------------
__device__ float g_h   [cT * cD];
__device__ float g_hn  [cT * cD];
__device__ float g_cos [cT * cDH];
__device__ float g_sin [cT * cDH];
__device__ float g_logits[cT * cE];
__device__ float g_probs [cT * cE];
__device__ unsigned char g_mask[cT * cE];
__device__ int   g_kept_slot[cT * cE];
__device__ int   g_counts[cE];
__device__ int   g_etok[cE * cCAP];
__device__ float g_eout[(long)cE * cCAP * cD];
// pre-split fp16 hi/lo operands (K-contiguous rows)
__device__ __half g_xinh[(long)cE * cCAP * cD];
__device__ __half g_xinl[(long)cE * cCAP * cD];
__device__ __half g_midh[(long)cE * cCAP * cDFF];
__device__ __half g_midl[(long)cE * cCAP * cDFF];
__device__ __half g_w1h [(long)cE * cDFF * cD];   // [e][n][k]
__device__ __half g_w1l [(long)cE * cDFF * cD];
__device__ __half g_w2h [(long)cE * cD * cDFF];   // [e][n][k]
__device__ __half g_w2l [(long)cE * cD * cDFF];

// ---------------- common helpers ----------------
__device__ __forceinline__ uint32_t s2u(const void* p) {
    uint32_t a;
    asm("{ .reg .u64 t; cvta.to.shared.u64 t, %1; cvt.u32.u64 %0, t; }" : "=r"(a) : "l"(p));
    return a;
}
__device__ __forceinline__ uint32_t cvt_tf32(float x) {
    uint32_t u; asm("cvt.rna.tf32.f32 %0, %1;" : "=r"(u) : "f"(x)); return u;
}
__device__ __forceinline__ void mma1688(float& c0, float& c1, float& c2, float& c3,
                                        uint32_t a0, uint32_t a1, uint32_t a2, uint32_t a3,
                                        uint32_t b0, uint32_t b1) {
    asm volatile(
        "mma.sync.aligned.m16n8k8.row.col.f32.tf32.tf32.f32 "
        "{%0,%1,%2,%3}, {%4,%5,%6,%7}, {%8,%9}, {%0,%1,%2,%3};"
        : "+f"(c0), "+f"(c1), "+f"(c2), "+f"(c3)
        : "r"(a0), "r"(a1), "r"(a2), "r"(a3), "r"(b0), "r"(b1));
}
__device__ __forceinline__ void mma16816(float& c0, float& c1, float& c2, float& c3,
                                         uint32_t a0, uint32_t a1, uint32_t a2, uint32_t a3,
                                         uint32_t b0, uint32_t b1) {
    asm volatile(
        "mma.sync.aligned.m16n8k16.row.col.f32.f16.f16.f32 "
        "{%0,%1,%2,%3}, {%4,%5,%6,%7}, {%8,%9}, {%0,%1,%2,%3};"
        : "+f"(c0), "+f"(c1), "+f"(c2), "+f"(c3)
        : "r"(a0), "r"(a1), "r"(a2), "r"(a3), "r"(b0), "r"(b1));
}
__device__ __forceinline__ void cpa16(uint32_t dst, const void* src, int sz) {
    asm volatile("cp.async.cg.shared.global [%0], [%1], 16, %2;"
                 :: "r"(dst), "l"(src), "r"(sz) : "memory");
}
__device__ __forceinline__ void split_h(float x, __half& hi, __half& lo) {
    hi = __float2half_rn(x);
    lo = __float2half_rn(x - __half2float(hi));
}
__device__ __forceinline__ float gelu1(float x) {
    return 0.5f * x * (1.0f + tanhf(0.7978845608028654f * (x + 0.044715f * x * x * x)));
}

// ---------------- small kernels ----------------
__global__ void rope_init_kernel() {
    int t = blockIdx.x;
    int i = threadIdx.x;
    int j = 2 * (i & 31);
    float inv = powf(10000.0f, -(float)j / (float)cDH);
    float fr  = (float)t * inv;
    g_cos[t * cDH + i] = cosf(fr);
    g_sin[t * cDH + i] = sinf(fr);
}

__global__ void embed_gather_kernel(const int* __restrict__ ids,
                                    const float* __restrict__ ew) {
    long idx = (long)blockIdx.x * blockDim.x + threadIdx.x;
    if (idx >= (long)cT * cD) return;
    int t = (int)(idx >> 10);
    int d = (int)(idx & (cD - 1));
    g_h[idx] = ew[(long)ids[t] * cD + d];
}

__global__ void router_logits_kernel(const float* __restrict__ wr) {
    int t    = blockIdx.x;
    int e    = threadIdx.x >> 5;
    int lane = threadIdx.x & 31;
    float s = 0.f;
    const float* hp = &g_h[(long)t * cD];
    for (int d = lane; d < cD; d += 32)
        s += hp[d] * wr[(long)d * cE + e];
    #pragma unroll
    for (int o = 16; o; o >>= 1) s += __shfl_down_sync(0xffffffffu, s, o);
    if (lane == 0) g_logits[t * cE + e] = s;
}

__global__ void token_route_kernel() {
    int t = blockIdx.x * blockDim.x + threadIdx.x;
    if (t >= cT) return;
    float l[cE];
    #pragma unroll
    for (int e = 0; e < cE; e++) l[e] = g_logits[t * cE + e];
    int i1 = 0; float v1 = l[0];
    #pragma unroll
    for (int e = 1; e < cE; e++) if (l[e] > v1) { v1 = l[e]; i1 = e; }
    int i2 = -1; float v2 = -INFINITY;
    #pragma unroll
    for (int e = 0; e < cE; e++) if (e != i1 && l[e] > v2) { v2 = l[e]; i2 = e; }
    float sum = 0.f; float p[cE];
    #pragma unroll
    for (int e = 0; e < cE; e++) { p[e] = expf(l[e] - v1); sum += p[e]; }
    float invs = 1.0f / sum;
    #pragma unroll
    for (int e = 0; e < cE; e++) {
        g_probs[t * cE + e] = p[e] * invs;
        g_mask [t * cE + e] = (e == i1 || e == i2) ? 1 : 0;
        g_kept_slot[t * cE + e] = -1;
    }
    if (t < cE) g_counts[t] = 0;
}

__global__ void capacity_kernel() {
    int e = blockIdx.x;
    __shared__ int   cnt;
    __shared__ int   idx[cT];
    __shared__ float val[cT];
    if (threadIdx.x == 0) cnt = 0;
    __syncthreads();
    for (int t = threadIdx.x; t < cT; t += blockDim.x) {
        if (g_mask[t * cE + e]) {
            int p = atomicAdd(&cnt, 1);
            idx[p] = t;
            val[p] = g_logits[t * cE + e];
        }
    }
    __syncthreads();
    int n = cnt;
    for (int i = threadIdx.x; i < n; i += blockDim.x) {
        float v = val[i]; int t = idx[i];
        int rank = 0;
        for (int j = 0; j < n; j++) {
            float u = val[j]; int s = idx[j];
            rank += (u > v || (u == v && s < t)) ? 1 : 0;
        }
        if (rank < cCAP) {
            int slot = atomicAdd(&g_counts[e], 1);
            g_etok[e * cCAP + slot] = t;
            g_kept_slot[t * cE + e] = slot;
        }
    }
}

// gather + RoPE + fp16 hi/lo split (pairs of adjacent d)
__global__ void gather_rope_kernel() {
    int c = blockIdx.x;
    int e = blockIdx.y;
    if (c >= g_counts[e]) return;
    int t = g_etok[e * cCAP + c];
    __shared__ float x[cD];
    for (int d = threadIdx.x; d < cD; d += blockDim.x) x[d] = g_h[(long)t * cD + d];
    __syncthreads();
    const float* cs = &g_cos[t * cDH];
    const float* sn = &g_sin[t * cDH];
    long base = ((long)(e * cCAP + c)) * cD;
    for (int dp = threadIdx.x; dp < cD / 2; dp += blockDim.x) {
        int d0 = dp * 2;
        float o[2];
        #pragma unroll
        for (int q = 0; q < 2; q++) {
            int d = d0 + q;
            int i = d & (cDH - 1);
            float r = (i < 32) ? -x[d + 32] : x[d - 32];
            o[q] = x[d] * cs[i] + r * sn[i];
        }
        __half h0, l0, h1, l1;
        split_h(o[0], h0, l0);
        split_h(o[1], h1, l1);
        *(__half2*)&g_xinh[base + d0] = __halves2half2(h0, h1);
        *(__half2*)&g_xinl[base + d0] = __halves2half2(l0, l1);
    }
}

__global__ void combine_kernel() {
    int t = blockIdx.x;
    int ne = 0;
    int ks[cK]; float kp[cK]; int ke[cK];
    float rho = 0.f;
    #pragma unroll
    for (int e = 0; e < cE; e++) {
        int s = g_kept_slot[t * cE + e];
        if (s >= 0) {
            float p = g_probs[t * cE + e];
            rho += p;
            if (ne < cK) { ke[ne] = e; ks[ne] = s; kp[ne] = p; ne++; }
        }
    }
    for (int d = threadIdx.x; d < cD; d += blockDim.x) {
        float hv = g_h[(long)t * cD + d];
        float comb = 0.f;
        for (int q = 0; q < ne; q++)
            comb += kp[q] * g_eout[((long)(ke[q] * cCAP + ks[q])) * cD + d];
        g_h[(long)t * cD + d] = hv + comb - rho * hv;
    }
}

__global__ void rmsnorm_kernel(const float* __restrict__ lns) {
    int t = blockIdx.x;
    __shared__ float red[256];
    float s = 0.f;
    for (int d = threadIdx.x; d < cD; d += 256) {
        float v = g_h[(long)t * cD + d];
        s += v * v;
    }
    red[threadIdx.x] = s;
    __syncthreads();
    #pragma unroll
    for (int o = 128; o; o >>= 1) {
        if (threadIdx.x < o) red[threadIdx.x] += red[threadIdx.x + o];
        __syncthreads();
    }
    float inv = rsqrtf(red[0] / (float)cD + 1e-6f);
    for (int d = threadIdx.x; d < cD; d += 256)
        g_hn[(long)t * cD + d] = g_h[(long)t * cD + d] * lns[d] * inv;
}

// pre-split + transpose weights: in [R][C] fp32 (R=K rows) -> oh/ol [C][R] fp16
__global__ void split_transpose_kernel(const float* __restrict__ in,
                                       __half* __restrict__ oh, __half* __restrict__ ol,
                                       int R, int C) {
    __shared__ float tile[32][33];
    long eoff = (long)blockIdx.z * R * C;
    int c0 = blockIdx.x * 32, r0 = blockIdx.y * 32;
    int x = threadIdx.x, y = threadIdx.y;       // 32 x 8
    #pragma unroll
    for (int i = 0; i < 32; i += 8)
        tile[y + i][x] = in[eoff + (long)(r0 + y + i) * C + c0 + x];
    __syncthreads();
    if (x < 16) {
        #pragma unroll
        for (int i = 0; i < 32; i += 8) {
            int nl = y + i;
            float v0 = tile[2 * x][nl];
            float v1 = tile[2 * x + 1][nl];
            __half h0, l0, h1, l1;
            split_h(v0, h0, l0);
            split_h(v1, h1, l1);
            long o = eoff + (long)(c0 + nl) * R + r0 + 2 * x;
            *(__half2*)&oh[o] = __halves2half2(h0, h1);
            *(__half2*)&ol[o] = __halves2half2(l0, l1);
        }
    }
}

// ---------------- pre-split fp16x3 GEMM ----------------
// C = act(A @ B^T): A[M][K] fp16 hi/lo, B[N][K] fp16 hi/lo (K contiguous both).
// BM=BN=128, BK=32, 8 warps (4Mx2N), warp tile 32x64, 2-stage cp.async, 80KB smem.
constexpr int HSTR  = 20;                    // b32 row stride (16 used + 4 pad)
constexpr int HSEG  = 128 * HSTR;            // 2560 b32
constexpr int HSTAGE= 4 * HSEG;              // Ahi Alo Bhi Blo
constexpr int HGEMM_SMEM = 2 * HSTAGE * 4;   // 81920 B

template<int ACT, int OUTF16>
__global__ void __launch_bounds__(256, 1)
hgemm_ps(const __half* __restrict__ Ah, const __half* __restrict__ Al,
         const __half* __restrict__ Bh, const __half* __restrict__ Bl,
         float* __restrict__ Cf, __half* __restrict__ Ch, __half* __restrict__ Cl,
         int Kd, int ldc,
         long sA, long sB, long sC, const int* __restrict__ Mvec)
{
    extern __shared__ uint32_t sh[];
    int e  = blockIdx.z;
    int Me = Mvec[e];
    int bm = blockIdx.y * 128;
    if (bm >= Me) return;
    int bn = blockIdx.x * 128;
    const __half* Ahp = Ah + (long)e * sA;
    const __half* Alp = Al + (long)e * sA;
    const __half* Bhp = Bh + (long)e * sB;
    const __half* Blp = Bl + (long)e * sB;

    int tid = threadIdx.x;
    int wid = tid >> 5, lane = tid & 31;
    int g   = lane >> 2, tg = lane & 3;
    int wm  = (wid & 3) * 32;
    int wn  = (wid >> 2) * 64;

    uint32_t smu = s2u(sh);

    auto load_stage = [&](int s, int k0) {
        uint32_t b0 = smu + (s * HSTAGE) * 4;
        #pragma unroll
        for (int j = 0; j < 2; j++) {
            int q = tid + 256 * j;
            int row = q >> 2, c4 = q & 3;
            int ok = (bm + row) < Me;
            long so = (long)(bm + row) * Kd + k0 + c4 * 8;
            uint32_t doff = (row * HSTR + c4 * 4) * 4;
            cpa16(b0 + doff,                Ahp + so, ok ? 16 : 0);
            cpa16(b0 + HSEG * 4 + doff,     Alp + so, ok ? 16 : 0);
        }
        #pragma unroll
        for (int j = 0; j < 2; j++) {
            int q = tid + 256 * j;
            int row = q >> 2, c4 = q & 3;
            long so = (long)(bn + row) * Kd + k0 + c4 * 8;
            uint32_t doff = (row * HSTR + c4 * 4) * 4;
            cpa16(b0 + HSEG * 8 + doff,     Bhp + so, 16);
            cpa16(b0 + HSEG * 12 + doff,    Blp + so, 16);
        }
        asm volatile("cp.async.commit_group;" ::: "memory");
    };

    float c[2][8][4];
    #pragma unroll
    for (int mi = 0; mi < 2; mi++)
        #pragma unroll
        for (int ni = 0; ni < 8; ni++)
            #pragma unroll
            for (int q = 0; q < 4; q++) c[mi][ni][q] = 0.f;

    int nK = Kd >> 5;
    load_stage(0, 0);
    load_stage(1, 32);

    for (int i = 0; i < nK; i++) {
        asm volatile("cp.async.wait_group 1;" ::: "memory");
        __syncthreads();

        const uint32_t* Ahi = sh + (i & 1) * HSTAGE;
        const uint32_t* Alo = Ahi + HSEG;
        const uint32_t* Bhi = Alo + HSEG;
        const uint32_t* Blo = Bhi + HSEG;

        #pragma unroll
        for (int ks = 0; ks < 2; ks++) {
            int ko = ks * 8;
            uint32_t ah[2][4], al[2][4];
            #pragma unroll
            for (int mi = 0; mi < 2; mi++) {
                int r0 = wm + mi * 16 + g;
                int o0 = r0 * HSTR + ko + tg;
                int o1 = (r0 + 8) * HSTR + ko + tg;
                ah[mi][0] = Ahi[o0];     ah[mi][1] = Ahi[o1];
                ah[mi][2] = Ahi[o0 + 4]; ah[mi][3] = Ahi[o1 + 4];
                al[mi][0] = Alo[o0];     al[mi][1] = Alo[o1];
                al[mi][2] = Alo[o0 + 4]; al[mi][3] = Alo[o1 + 4];
            }
            uint32_t bh[8][2], bl[8][2];
            #pragma unroll
            for (int ni = 0; ni < 8; ni++) {
                int n = wn + ni * 8 + g;
                int o = n * HSTR + ko + tg;
                bh[ni][0] = Bhi[o]; bh[ni][1] = Bhi[o + 4];
                bl[ni][0] = Blo[o]; bl[ni][1] = Blo[o + 4];
            }
            #pragma unroll
            for (int mi = 0; mi < 2; mi++)
                #pragma unroll
                for (int ni = 0; ni < 8; ni++)
                    mma16816(c[mi][ni][0], c[mi][ni][1], c[mi][ni][2], c[mi][ni][3],
                             ah[mi][0], ah[mi][1], ah[mi][2], ah[mi][3],
                             bh[ni][0], bh[ni][1]);
            #pragma unroll
            for (int mi = 0; mi < 2; mi++)
                #pragma unroll
                for (int ni = 0; ni < 8; ni++)
                    mma16816(c[mi][ni][0], c[mi][ni][1], c[mi][ni][2], c[mi][ni][3],
                             ah[mi][0], ah[mi][1], ah[mi][2], ah[mi][3],
                             bl[ni][0], bl[ni][1]);
            #pragma unroll
            for (int mi = 0; mi < 2; mi++)
                #pragma unroll
                for (int ni = 0; ni < 8; ni++)
                    mma16816(c[mi][ni][0], c[mi][ni][1], c[mi][ni][2], c[mi][ni][3],
                             al[mi][0], al[mi][1], al[mi][2], al[mi][3],
                             bh[ni][0], bh[ni][1]);
        }
        __syncthreads();
        if (i + 2 < nK) load_stage(i & 1, (i + 2) * 32);
        else asm volatile("cp.async.commit_group;" ::: "memory");
    }

    #pragma unroll
    for (int mi = 0; mi < 2; mi++) {
        int r0 = bm + wm + mi * 16 + g;
        #pragma unroll
        for (int ni = 0; ni < 8; ni++) {
            int col = bn + wn + ni * 8 + tg * 2;
            float v0 = c[mi][ni][0], v1 = c[mi][ni][1];
            float v2 = c[mi][ni][2], v3 = c[mi][ni][3];
            if (ACT) { v0 = gelu1(v0); v1 = gelu1(v1); v2 = gelu1(v2); v3 = gelu1(v3); }
            if (OUTF16) {
                __half h0, l0, h1, l1;
                if (r0 < Me) {
                    split_h(v0, h0, l0); split_h(v1, h1, l1);
                    long o = (long)e * sC + (long)r0 * ldc + col;
                    *(__half2*)&Ch[o] = __halves2half2(h0, h1);
                    *(__half2*)&Cl[o] = __halves2half2(l0, l1);
                }
                if (r0 + 8 < Me) {
                    split_h(v2, h0, l0); split_h(v3, h1, l1);
                    long o = (long)e * sC + (long)(r0 + 8) * ldc + col;
                    *(__half2*)&Ch[o] = __halves2half2(h0, h1);
                    *(__half2*)&Cl[o] = __halves2half2(l0, l1);
                }
            } else {
                long eb = (long)e * sC;
                if (r0 < Me)     *(float2*)&Cf[eb + (long)r0 * ldc + col]       = make_float2(v0, v1);
                if (r0 + 8 < Me) *(float2*)&Cf[eb + (long)(r0 + 8) * ldc + col] = make_float2(v2, v3);
            }
        }
    }
}

// ---------------- tf32 single-pass GEMM for logits ----------------
constexpr int AST  = 36;
constexpr int A_FLOATS = 128 * AST;
constexpr int STG_FLOATS = 2 * A_FLOATS;
constexpr int TGEMM_SMEM = 3 * STG_FLOATS * 4;

__global__ void __launch_bounds__(256, 1)
tgemm_logits(const float* __restrict__ A, const float* __restrict__ B, float* __restrict__ C,
             int Kd, int lda, int ldb, int ldc, int M)
{
    extern __shared__ float sm[];
    int bm = blockIdx.y * 128;
    int bn = blockIdx.x * 128;

    int tid  = threadIdx.x;
    int wid  = tid >> 5, lane = tid & 31;
    int g    = lane >> 2, tg = lane & 3;
    int wm   = (wid & 3) * 32;
    int wn   = (wid >> 2) * 64;

    uint32_t smu = s2u(sm);

    auto load_stage = [&](int s, int k0) {
        uint32_t sa = smu + (s * STG_FLOATS) * 4;
        uint32_t sb = sa + A_FLOATS * 4;
        #pragma unroll
        for (int j = 0; j < 4; j++) {
            int q = tid + 256 * j;
            int row = q >> 3, c4 = q & 7;
            cpa16(sa + (row * AST + c4 * 4) * 4, A + (long)(bm + row) * lda + k0 + c4 * 4, 16);
        }
        #pragma unroll
        for (int j = 0; j < 4; j++) {
            int q = tid + 256 * j;
            int row = q >> 3, c4 = q & 7;
            cpa16(sb + (row * AST + c4 * 4) * 4, B + (long)(bn + row) * ldb + k0 + c4 * 4, 16);
        }
        asm volatile("cp.async.commit_group;" ::: "memory");
    };

    float c[2][8][4];
    #pragma unroll
    for (int mi = 0; mi < 2; mi++)
        #pragma unroll
        for (int ni = 0; ni < 8; ni++)
            #pragma unroll
            for (int q = 0; q < 4; q++) c[mi][ni][q] = 0.f;

    int nK = Kd >> 5;
    load_stage(0, 0);
    load_stage(1, 32);

    for (int i = 0; i < nK; i++) {
        asm volatile("cp.async.wait_group 1;" ::: "memory");
        __syncthreads();
        if (i + 2 < nK) load_stage((i + 2) % 3, (i + 2) * 32);
        else asm volatile("cp.async.commit_group;" ::: "memory");

        const float* As = sm + (i % 3) * STG_FLOATS;
        const float* Bs = As + A_FLOATS;

        #pragma unroll
        for (int ks = 0; ks < 4; ks++) {
            int kb = ks * 8;
            uint32_t a[2][4], b[8][2];
            #pragma unroll
            for (int mi = 0; mi < 2; mi++) {
                int r0 = wm + mi * 16 + g;
                a[mi][0] = cvt_tf32(As[r0 * AST + kb + tg]);
                a[mi][1] = cvt_tf32(As[(r0 + 8) * AST + kb + tg]);
                a[mi][2] = cvt_tf32(As[r0 * AST + kb + tg + 4]);
                a[mi][3] = cvt_tf32(As[(r0 + 8) * AST + kb + tg + 4]);
            }
            #pragma unroll
            for (int ni = 0; ni < 8; ni++) {
                int n = wn + ni * 8 + g;
                b[ni][0] = cvt_tf32(Bs[n * AST + kb + tg]);
                b[ni][1] = cvt_tf32(Bs[n * AST + kb + tg + 4]);
            }
            #pragma unroll
            for (int mi = 0; mi < 2; mi++)
                #pragma unroll
                for (int ni = 0; ni < 8; ni++)
                    mma1688(c[mi][ni][0], c[mi][ni][1], c[mi][ni][2], c[mi][ni][3],
                            a[mi][0], a[mi][1], a[mi][2], a[mi][3],
                            b[ni][0], b[ni][1]);
        }
        __syncthreads();
    }

    #pragma unroll
    for (int mi = 0; mi < 2; mi++) {
        int r0 = bm + wm + mi * 16 + g;
        #pragma unroll
        for (int ni = 0; ni < 8; ni++) {
            int col = bn + wn + ni * 8 + tg * 2;
            *(float2*)&C[(long)r0 * ldc + col]       = make_float2(c[mi][ni][0], c[mi][ni][1]);
            *(float2*)&C[(long)(r0 + 8) * ldc + col] = make_float2(c[mi][ni][2], c[mi][ni][3]);
        }
    }
}

// ---------------- launch ----------------
extern "C" void kernel_launch(void* const* d_in, const int* in_sizes, int n_in,
                              void* d_out, int out_size) {
    const int*   ids      = (const int*)  d_in[0];
    const float* embed_w  = (const float*)d_in[1];
    const float* router_w = (const float*)d_in[2];
    const float* w1       = (const float*)d_in[3];
    const float* w2       = (const float*)d_in[4];
    const float* lns      = (const float*)d_in[5];
    float* out = (float*)d_out;

    float *p_eout, *p_hn;
    __half *p_xinh, *p_xinl, *p_midh, *p_midl, *p_w1h, *p_w1l, *p_w2h, *p_w2l;
    int   *p_counts;
    cudaGetSymbolAddress((void**)&p_eout,   g_eout);
    cudaGetSymbolAddress((void**)&p_hn,     g_hn);
    cudaGetSymbolAddress((void**)&p_xinh,   g_xinh);
    cudaGetSymbolAddress((void**)&p_xinl,   g_xinl);
    cudaGetSymbolAddress((void**)&p_midh,   g_midh);
    cudaGetSymbolAddress((void**)&p_midl,   g_midl);
    cudaGetSymbolAddress((void**)&p_w1h,    g_w1h);
    cudaGetSymbolAddress((void**)&p_w1l,    g_w1l);
    cudaGetSymbolAddress((void**)&p_w2h,    g_w2h);
    cudaGetSymbolAddress((void**)&p_w2l,    g_w2l);
    cudaGetSymbolAddress((void**)&p_counts, g_counts);

    cudaFuncSetAttribute(hgemm_ps<1,1>, cudaFuncAttributeMaxDynamicSharedMemorySize, HGEMM_SMEM);
    cudaFuncSetAttribute(hgemm_ps<0,0>, cudaFuncAttributeMaxDynamicSharedMemorySize, HGEMM_SMEM);
    cudaFuncSetAttribute(tgemm_logits, cudaFuncAttributeMaxDynamicSharedMemorySize, TGEMM_SMEM);

    rope_init_kernel<<<cT, 64>>>();
    embed_gather_kernel<<<(int)(((long)cT * cD + 255) / 256), 256>>>(ids, embed_w);

    // pre-split + transpose weights to fp16 hi/lo [N][K] (once; reused both hops)
    split_transpose_kernel<<<dim3(cDFF / 32, cD / 32, cE), dim3(32, 8)>>>(w1, p_w1h, p_w1l, cD, cDFF);
    split_transpose_kernel<<<dim3(cD / 32, cDFF / 32, cE), dim3(32, 8)>>>(w2, p_w2h, p_w2l, cDFF, cD);

    for (int hop = 0; hop < cHOPS; hop++) {
        router_logits_kernel<<<cT, 512>>>(router_w + (long)hop * cD * cE);
        token_route_kernel<<<(cT + 255) / 256, 256>>>();
        capacity_kernel<<<cE, 256>>>();
        gather_rope_kernel<<<dim3(cCAP, cE), 256>>>();
        // mid(h/l) = gelu(xin @ w1^T): M=cnt_e, N=4096, K=1024
        hgemm_ps<1,1><<<dim3(cDFF / 128, cCAP / 128, cE), 256, HGEMM_SMEM>>>(
            p_xinh, p_xinl, p_w1h, p_w1l,
            nullptr, p_midh, p_midl,
            cD, cDFF,
            (long)cCAP * cD, (long)cDFF * cD, (long)cCAP * cDFF, p_counts);
        // eout = mid @ w2^T: M=cnt_e, N=1024, K=4096
        hgemm_ps<0,0><<<dim3(cD / 128, cCAP / 128, cE), 256, HGEMM_SMEM>>>(
            p_midh, p_midl, p_w2h, p_w2l,
            p_eout, nullptr, nullptr,
            cDFF, cD,
            (long)cCAP * cDFF, (long)cD * cDFF, (long)cCAP * cD, p_counts);
        combine_kernel<<<cT, 256>>>();
    }

    rmsnorm_kernel<<<cT, 256>>>(lns);
    // logits = hn @ embed_w^T: M=2048, N=32000, K=1024
    tgemm_logits<<<dim3(cV / 128, cT / 128, 1), 256, TGEMM_SMEM>>>(
        p_hn, embed_w, out, cD, cD, cD, cV, cT);
}

// round 7
// speedup vs baseline: 3.1258x; 1.1824x over previous
#include <cuda_runtime.h>
#include <cuda_fp16.h>
#include <math.h>
#include <stdint.h>

// ---------------- problem constants ----------------
constexpr int cT   = 2048;
constexpr int cD   = 1024;
constexpr int cV   = 32000;
constexpr int cE   = 16;
constexpr int cK   = 2;
constexpr int cCAP = 512;
constexpr int cDH  = 64;
constexpr int cDFF = 4096;
constexpr int cHOPS= 2;

// ---------------- device scratch ----------------
__device__ float g_h   [cT * cD];
__device__ float g_cos [cT * cDH];
__device__ float g_sin [cT * cDH];
__device__ float g_logits[cT * cE];
__device__ float g_probs [cT * cE];
__device__ unsigned char g_mask[cT * cE];
__device__ int   g_kept_slot[cT * cE];
__device__ int   g_counts[cE];
__device__ int   g_etok[cE * cCAP];
__device__ float g_eout[(long)cE * cCAP * cD];
// pre-split fp16 hi/lo operands (K-contiguous rows)
__device__ __half g_xinh[(long)cE * cCAP * cD];
__device__ __half g_xinl[(long)cE * cCAP * cD];
__device__ __half g_midh[(long)cE * cCAP * cDFF];
__device__ __half g_midl[(long)cE * cCAP * cDFF];
__device__ __half g_w1h [(long)cE * cDFF * cD];   // [e][n][k]
__device__ __half g_w1l [(long)cE * cDFF * cD];
__device__ __half g_w2h [(long)cE * cD * cDFF];   // [e][n][k]
__device__ __half g_w2l [(long)cE * cD * cDFF];
// fp16 operands for logits GEMM
__device__ __half g_hnh [cT * cD];                // normalized hidden, fp16
__device__ __half g_ewh [(long)cV * cD];          // embed weights, fp16 [V][K]

// ---------------- common helpers ----------------
__device__ __forceinline__ uint32_t s2u(const void* p) {
    uint32_t a;
    asm("{ .reg .u64 t; cvta.to.shared.u64 t, %1; cvt.u32.u64 %0, t; }" : "=r"(a) : "l"(p));
    return a;
}
__device__ __forceinline__ void mma16816(float& c0, float& c1, float& c2, float& c3,
                                         uint32_t a0, uint32_t a1, uint32_t a2, uint32_t a3,
                                         uint32_t b0, uint32_t b1) {
    asm volatile(
        "mma.sync.aligned.m16n8k16.row.col.f32.f16.f16.f32 "
        "{%0,%1,%2,%3}, {%4,%5,%6,%7}, {%8,%9}, {%0,%1,%2,%3};"
        : "+f"(c0), "+f"(c1), "+f"(c2), "+f"(c3)
        : "r"(a0), "r"(a1), "r"(a2), "r"(a3), "r"(b0), "r"(b1));
}
__device__ __forceinline__ void cpa16(uint32_t dst, const void* src, int sz) {
    asm volatile("cp.async.cg.shared.global [%0], [%1], 16, %2;"
                 :: "r"(dst), "l"(src), "r"(sz) : "memory");
}
__device__ __forceinline__ void split_h(float x, __half& hi, __half& lo) {
    hi = __float2half_rn(x);
    lo = __float2half_rn(x - __half2float(hi));
}
__device__ __forceinline__ float gelu1(float x) {
    return 0.5f * x * (1.0f + tanhf(0.7978845608028654f * (x + 0.044715f * x * x * x)));
}

// ---------------- small kernels ----------------
__global__ void rope_init_kernel() {
    int t = blockIdx.x;
    int i = threadIdx.x;
    int j = 2 * (i & 31);
    float inv = powf(10000.0f, -(float)j / (float)cDH);
    float fr  = (float)t * inv;
    g_cos[t * cDH + i] = cosf(fr);
    g_sin[t * cDH + i] = sinf(fr);
}

__global__ void embed_gather_kernel(const int* __restrict__ ids,
                                    const float* __restrict__ ew) {
    long idx = (long)blockIdx.x * blockDim.x + threadIdx.x;
    if (idx >= (long)cT * cD) return;
    int t = (int)(idx >> 10);
    int d = (int)(idx & (cD - 1));
    g_h[idx] = ew[(long)ids[t] * cD + d];
}

__global__ void ew_half_kernel(const float* __restrict__ ew) {
    long idx = ((long)blockIdx.x * blockDim.x + threadIdx.x) * 2;
    if (idx >= (long)cV * cD) return;
    float2 v = *(const float2*)&ew[idx];
    *(__half2*)&g_ewh[idx] = __halves2half2(__float2half_rn(v.x), __float2half_rn(v.y));
}

__global__ void router_logits_kernel(const float* __restrict__ wr) {
    int t    = blockIdx.x;
    int e    = threadIdx.x >> 5;
    int lane = threadIdx.x & 31;
    float s = 0.f;
    const float* hp = &g_h[(long)t * cD];
    for (int d = lane; d < cD; d += 32)
        s += hp[d] * wr[(long)d * cE + e];
    #pragma unroll
    for (int o = 16; o; o >>= 1) s += __shfl_down_sync(0xffffffffu, s, o);
    if (lane == 0) g_logits[t * cE + e] = s;
}

__global__ void token_route_kernel() {
    int t = blockIdx.x * blockDim.x + threadIdx.x;
    if (t >= cT) return;
    float l[cE];
    #pragma unroll
    for (int e = 0; e < cE; e++) l[e] = g_logits[t * cE + e];
    int i1 = 0; float v1 = l[0];
    #pragma unroll
    for (int e = 1; e < cE; e++) if (l[e] > v1) { v1 = l[e]; i1 = e; }
    int i2 = -1; float v2 = -INFINITY;
    #pragma unroll
    for (int e = 0; e < cE; e++) if (e != i1 && l[e] > v2) { v2 = l[e]; i2 = e; }
    float sum = 0.f; float p[cE];
    #pragma unroll
    for (int e = 0; e < cE; e++) { p[e] = expf(l[e] - v1); sum += p[e]; }
    float invs = 1.0f / sum;
    #pragma unroll
    for (int e = 0; e < cE; e++) {
        g_probs[t * cE + e] = p[e] * invs;
        g_mask [t * cE + e] = (e == i1 || e == i2) ? 1 : 0;
        g_kept_slot[t * cE + e] = -1;
    }
    if (t < cE) g_counts[t] = 0;
}

__global__ void capacity_kernel() {
    int e = blockIdx.x;
    __shared__ int   cnt;
    __shared__ int   idx[cT];
    __shared__ float val[cT];
    if (threadIdx.x == 0) cnt = 0;
    __syncthreads();
    for (int t = threadIdx.x; t < cT; t += blockDim.x) {
        if (g_mask[t * cE + e]) {
            int p = atomicAdd(&cnt, 1);
            idx[p] = t;
            val[p] = g_logits[t * cE + e];
        }
    }
    __syncthreads();
    int n = cnt;
    for (int i = threadIdx.x; i < n; i += blockDim.x) {
        float v = val[i]; int t = idx[i];
        int rank = 0;
        for (int j = 0; j < n; j++) {
            float u = val[j]; int s = idx[j];
            rank += (u > v || (u == v && s < t)) ? 1 : 0;
        }
        if (rank < cCAP) {
            int slot = atomicAdd(&g_counts[e], 1);
            g_etok[e * cCAP + slot] = t;
            g_kept_slot[t * cE + e] = slot;
        }
    }
}

// gather + RoPE + fp16 hi/lo split (pairs of adjacent d)
__global__ void gather_rope_kernel() {
    int c = blockIdx.x;
    int e = blockIdx.y;
    if (c >= g_counts[e]) return;
    int t = g_etok[e * cCAP + c];
    __shared__ float x[cD];
    for (int d = threadIdx.x; d < cD; d += blockDim.x) x[d] = g_h[(long)t * cD + d];
    __syncthreads();
    const float* cs = &g_cos[t * cDH];
    const float* sn = &g_sin[t * cDH];
    long base = ((long)(e * cCAP + c)) * cD;
    for (int dp = threadIdx.x; dp < cD / 2; dp += blockDim.x) {
        int d0 = dp * 2;
        float o[2];
        #pragma unroll
        for (int q = 0; q < 2; q++) {
            int d = d0 + q;
            int i = d & (cDH - 1);
            float r = (i < 32) ? -x[d + 32] : x[d - 32];
            o[q] = x[d] * cs[i] + r * sn[i];
        }
        __half h0, l0, h1, l1;
        split_h(o[0], h0, l0);
        split_h(o[1], h1, l1);
        *(__half2*)&g_xinh[base + d0] = __halves2half2(h0, h1);
        *(__half2*)&g_xinl[base + d0] = __halves2half2(l0, l1);
    }
}

__global__ void combine_kernel() {
    int t = blockIdx.x;
    int ne = 0;
    int ks[cK]; float kp[cK]; int ke[cK];
    float rho = 0.f;
    #pragma unroll
    for (int e = 0; e < cE; e++) {
        int s = g_kept_slot[t * cE + e];
        if (s >= 0) {
            float p = g_probs[t * cE + e];
            rho += p;
            if (ne < cK) { ke[ne] = e; ks[ne] = s; kp[ne] = p; ne++; }
        }
    }
    for (int d = threadIdx.x; d < cD; d += blockDim.x) {
        float hv = g_h[(long)t * cD + d];
        float comb = 0.f;
        for (int q = 0; q < ne; q++)
            comb += kp[q] * g_eout[((long)(ke[q] * cCAP + ks[q])) * cD + d];
        g_h[(long)t * cD + d] = hv + comb - rho * hv;
    }
}

// RMSNorm -> fp16 output for logits GEMM
__global__ void rmsnorm_kernel(const float* __restrict__ lns) {
    int t = blockIdx.x;
    __shared__ float red[256];
    float s = 0.f;
    for (int d = threadIdx.x; d < cD; d += 256) {
        float v = g_h[(long)t * cD + d];
        s += v * v;
    }
    red[threadIdx.x] = s;
    __syncthreads();
    #pragma unroll
    for (int o = 128; o; o >>= 1) {
        if (threadIdx.x < o) red[threadIdx.x] += red[threadIdx.x + o];
        __syncthreads();
    }
    float inv = rsqrtf(red[0] / (float)cD + 1e-6f);
    for (int d = threadIdx.x; d < cD; d += 256)
        g_hnh[(long)t * cD + d] =
            __float2half_rn(g_h[(long)t * cD + d] * lns[d] * inv);
}

// pre-split + transpose weights: in [R][C] fp32 (R=K rows) -> oh/ol [C][R] fp16
__global__ void split_transpose_kernel(const float* __restrict__ in,
                                       __half* __restrict__ oh, __half* __restrict__ ol,
                                       int R, int C) {
    __shared__ float tile[32][33];
    long eoff = (long)blockIdx.z * R * C;
    int c0 = blockIdx.x * 32, r0 = blockIdx.y * 32;
    int x = threadIdx.x, y = threadIdx.y;       // 32 x 8
    #pragma unroll
    for (int i = 0; i < 32; i += 8)
        tile[y + i][x] = in[eoff + (long)(r0 + y + i) * C + c0 + x];
    __syncthreads();
    if (x < 16) {
        #pragma unroll
        for (int i = 0; i < 32; i += 8) {
            int nl = y + i;
            float v0 = tile[2 * x][nl];
            float v1 = tile[2 * x + 1][nl];
            __half h0, l0, h1, l1;
            split_h(v0, h0, l0);
            split_h(v1, h1, l1);
            long o = eoff + (long)(c0 + nl) * R + r0 + 2 * x;
            *(__half2*)&oh[o] = __halves2half2(h0, h1);
            *(__half2*)&ol[o] = __halves2half2(l0, l1);
        }
    }
}

// ---------------- pre-split fp16x3 GEMM (experts) ----------------
constexpr int HSTR  = 20;                    // b32 row stride (16 used + 4 pad)
constexpr int HSEG  = 128 * HSTR;            // 2560 b32
constexpr int HSTAGE= 4 * HSEG;              // Ahi Alo Bhi Blo
constexpr int HGEMM_SMEM = 2 * HSTAGE * 4;   // 81920 B

template<int ACT, int OUTF16>
__global__ void __launch_bounds__(256, 1)
hgemm_ps(const __half* __restrict__ Ah, const __half* __restrict__ Al,
         const __half* __restrict__ Bh, const __half* __restrict__ Bl,
         float* __restrict__ Cf, __half* __restrict__ Ch, __half* __restrict__ Cl,
         int Kd, int ldc,
         long sA, long sB, long sC, const int* __restrict__ Mvec)
{
    extern __shared__ uint32_t sh[];
    int e  = blockIdx.z;
    int Me = Mvec[e];
    int bm = blockIdx.y * 128;
    if (bm >= Me) return;
    int bn = blockIdx.x * 128;
    const __half* Ahp = Ah + (long)e * sA;
    const __half* Alp = Al + (long)e * sA;
    const __half* Bhp = Bh + (long)e * sB;
    const __half* Blp = Bl + (long)e * sB;

    int tid = threadIdx.x;
    int wid = tid >> 5, lane = tid & 31;
    int g   = lane >> 2, tg = lane & 3;
    int wm  = (wid & 3) * 32;
    int wn  = (wid >> 2) * 64;

    uint32_t smu = s2u(sh);

    auto load_stage = [&](int s, int k0) {
        uint32_t b0 = smu + (s * HSTAGE) * 4;
        #pragma unroll
        for (int j = 0; j < 2; j++) {
            int q = tid + 256 * j;
            int row = q >> 2, c4 = q & 3;
            int ok = (bm + row) < Me;
            long so = (long)(bm + row) * Kd + k0 + c4 * 8;
            uint32_t doff = (row * HSTR + c4 * 4) * 4;
            cpa16(b0 + doff,                Ahp + so, ok ? 16 : 0);
            cpa16(b0 + HSEG * 4 + doff,     Alp + so, ok ? 16 : 0);
        }
        #pragma unroll
        for (int j = 0; j < 2; j++) {
            int q = tid + 256 * j;
            int row = q >> 2, c4 = q & 3;
            long so = (long)(bn + row) * Kd + k0 + c4 * 8;
            uint32_t doff = (row * HSTR + c4 * 4) * 4;
            cpa16(b0 + HSEG * 8 + doff,     Bhp + so, 16);
            cpa16(b0 + HSEG * 12 + doff,    Blp + so, 16);
        }
        asm volatile("cp.async.commit_group;" ::: "memory");
    };

    float c[2][8][4];
    #pragma unroll
    for (int mi = 0; mi < 2; mi++)
        #pragma unroll
        for (int ni = 0; ni < 8; ni++)
            #pragma unroll
            for (int q = 0; q < 4; q++) c[mi][ni][q] = 0.f;

    int nK = Kd >> 5;
    load_stage(0, 0);
    load_stage(1, 32);

    for (int i = 0; i < nK; i++) {
        asm volatile("cp.async.wait_group 1;" ::: "memory");
        __syncthreads();

        const uint32_t* Ahi = sh + (i & 1) * HSTAGE;
        const uint32_t* Alo = Ahi + HSEG;
        const uint32_t* Bhi = Alo + HSEG;
        const uint32_t* Blo = Bhi + HSEG;

        #pragma unroll
        for (int ks = 0; ks < 2; ks++) {
            int ko = ks * 8;
            uint32_t ah[2][4], al[2][4];
            #pragma unroll
            for (int mi = 0; mi < 2; mi++) {
                int r0 = wm + mi * 16 + g;
                int o0 = r0 * HSTR + ko + tg;
                int o1 = (r0 + 8) * HSTR + ko + tg;
                ah[mi][0] = Ahi[o0];     ah[mi][1] = Ahi[o1];
                ah[mi][2] = Ahi[o0 + 4]; ah[mi][3] = Ahi[o1 + 4];
                al[mi][0] = Alo[o0];     al[mi][1] = Alo[o1];
                al[mi][2] = Alo[o0 + 4]; al[mi][3] = Alo[o1 + 4];
            }
            uint32_t bh[8][2], bl[8][2];
            #pragma unroll
            for (int ni = 0; ni < 8; ni++) {
                int n = wn + ni * 8 + g;
                int o = n * HSTR + ko + tg;
                bh[ni][0] = Bhi[o]; bh[ni][1] = Bhi[o + 4];
                bl[ni][0] = Blo[o]; bl[ni][1] = Blo[o + 4];
            }
            #pragma unroll
            for (int mi = 0; mi < 2; mi++)
                #pragma unroll
                for (int ni = 0; ni < 8; ni++)
                    mma16816(c[mi][ni][0], c[mi][ni][1], c[mi][ni][2], c[mi][ni][3],
                             ah[mi][0], ah[mi][1], ah[mi][2], ah[mi][3],
                             bh[ni][0], bh[ni][1]);
            #pragma unroll
            for (int mi = 0; mi < 2; mi++)
                #pragma unroll
                for (int ni = 0; ni < 8; ni++)
                    mma16816(c[mi][ni][0], c[mi][ni][1], c[mi][ni][2], c[mi][ni][3],
                             ah[mi][0], ah[mi][1], ah[mi][2], ah[mi][3],
                             bl[ni][0], bl[ni][1]);
            #pragma unroll
            for (int mi = 0; mi < 2; mi++)
                #pragma unroll
                for (int ni = 0; ni < 8; ni++)
                    mma16816(c[mi][ni][0], c[mi][ni][1], c[mi][ni][2], c[mi][ni][3],
                             al[mi][0], al[mi][1], al[mi][2], al[mi][3],
                             bh[ni][0], bh[ni][1]);
        }
        __syncthreads();
        if (i + 2 < nK) load_stage(i & 1, (i + 2) * 32);
        else asm volatile("cp.async.commit_group;" ::: "memory");
    }

    #pragma unroll
    for (int mi = 0; mi < 2; mi++) {
        int r0 = bm + wm + mi * 16 + g;
        #pragma unroll
        for (int ni = 0; ni < 8; ni++) {
            int col = bn + wn + ni * 8 + tg * 2;
            float v0 = c[mi][ni][0], v1 = c[mi][ni][1];
            float v2 = c[mi][ni][2], v3 = c[mi][ni][3];
            if (ACT) { v0 = gelu1(v0); v1 = gelu1(v1); v2 = gelu1(v2); v3 = gelu1(v3); }
            if (OUTF16) {
                __half h0, l0, h1, l1;
                if (r0 < Me) {
                    split_h(v0, h0, l0); split_h(v1, h1, l1);
                    long o = (long)e * sC + (long)r0 * ldc + col;
                    *(__half2*)&Ch[o] = __halves2half2(h0, h1);
                    *(__half2*)&Cl[o] = __halves2half2(l0, l1);
                }
                if (r0 + 8 < Me) {
                    split_h(v2, h0, l0); split_h(v3, h1, l1);
                    long o = (long)e * sC + (long)(r0 + 8) * ldc + col;
                    *(__half2*)&Ch[o] = __halves2half2(h0, h1);
                    *(__half2*)&Cl[o] = __halves2half2(l0, l1);
                }
            } else {
                long eb = (long)e * sC;
                if (r0 < Me)     *(float2*)&Cf[eb + (long)r0 * ldc + col]       = make_float2(v0, v1);
                if (r0 + 8 < Me) *(float2*)&Cf[eb + (long)(r0 + 8) * ldc + col] = make_float2(v2, v3);
            }
        }
    }
}

// ---------------- fp16 single-pass GEMM for logits ----------------
// C = A @ B^T: A = g_hnh [T][K] fp16, B = g_ewh [V][K] fp16, C fp32.
// 40KB smem -> occupancy 2.
constexpr int LSTAGE = 2 * HSEG;                 // Ah + Bh
constexpr int LGEMM_SMEM = 2 * LSTAGE * 4;       // 40960 B

__global__ void __launch_bounds__(256, 2)
hgemm_logits(const __half* __restrict__ A, const __half* __restrict__ B,
             float* __restrict__ C, int Kd, int ldc)
{
    extern __shared__ uint32_t sh[];
    int bm = blockIdx.y * 128;
    int bn = blockIdx.x * 128;

    int tid = threadIdx.x;
    int wid = tid >> 5, lane = tid & 31;
    int g   = lane >> 2, tg = lane & 3;
    int wm  = (wid & 3) * 32;
    int wn  = (wid >> 2) * 64;

    uint32_t smu = s2u(sh);

    auto load_stage = [&](int s, int k0) {
        uint32_t b0 = smu + (s * LSTAGE) * 4;
        #pragma unroll
        for (int j = 0; j < 2; j++) {
            int q = tid + 256 * j;
            int row = q >> 2, c4 = q & 3;
            uint32_t doff = (row * HSTR + c4 * 4) * 4;
            cpa16(b0 + doff,            A + (long)(bm + row) * Kd + k0 + c4 * 8, 16);
            cpa16(b0 + HSEG * 4 + doff, B + (long)(bn + row) * Kd + k0 + c4 * 8, 16);
        }
        asm volatile("cp.async.commit_group;" ::: "memory");
    };

    float c[2][8][4];
    #pragma unroll
    for (int mi = 0; mi < 2; mi++)
        #pragma unroll
        for (int ni = 0; ni < 8; ni++)
            #pragma unroll
            for (int q = 0; q < 4; q++) c[mi][ni][q] = 0.f;

    int nK = Kd >> 5;
    load_stage(0, 0);
    load_stage(1, 32);

    for (int i = 0; i < nK; i++) {
        asm volatile("cp.async.wait_group 1;" ::: "memory");
        __syncthreads();

        const uint32_t* As = sh + (i & 1) * LSTAGE;
        const uint32_t* Bs = As + HSEG;

        #pragma unroll
        for (int ks = 0; ks < 2; ks++) {
            int ko = ks * 8;
            uint32_t a[2][4], b[8][2];
            #pragma unroll
            for (int mi = 0; mi < 2; mi++) {
                int r0 = wm + mi * 16 + g;
                int o0 = r0 * HSTR + ko + tg;
                int o1 = (r0 + 8) * HSTR + ko + tg;
                a[mi][0] = As[o0];     a[mi][1] = As[o1];
                a[mi][2] = As[o0 + 4]; a[mi][3] = As[o1 + 4];
            }
            #pragma unroll
            for (int ni = 0; ni < 8; ni++) {
                int n = wn + ni * 8 + g;
                int o = n * HSTR + ko + tg;
                b[ni][0] = Bs[o]; b[ni][1] = Bs[o + 4];
            }
            #pragma unroll
            for (int mi = 0; mi < 2; mi++)
                #pragma unroll
                for (int ni = 0; ni < 8; ni++)
                    mma16816(c[mi][ni][0], c[mi][ni][1], c[mi][ni][2], c[mi][ni][3],
                             a[mi][0], a[mi][1], a[mi][2], a[mi][3],
                             b[ni][0], b[ni][1]);
        }
        __syncthreads();
        if (i + 2 < nK) load_stage(i & 1, (i + 2) * 32);
        else asm volatile("cp.async.commit_group;" ::: "memory");
    }

    #pragma unroll
    for (int mi = 0; mi < 2; mi++) {
        int r0 = bm + wm + mi * 16 + g;
        #pragma unroll
        for (int ni = 0; ni < 8; ni++) {
            int col = bn + wn + ni * 8 + tg * 2;
            *(float2*)&C[(long)r0 * ldc + col]       = make_float2(c[mi][ni][0], c[mi][ni][1]);
            *(float2*)&C[(long)(r0 + 8) * ldc + col] = make_float2(c[mi][ni][2], c[mi][ni][3]);
        }
    }
}

// ---------------- launch ----------------
extern "C" void kernel_launch(void* const* d_in, const int* in_sizes, int n_in,
                              void* d_out, int out_size) {
    const int*   ids      = (const int*)  d_in[0];
    const float* embed_w  = (const float*)d_in[1];
    const float* router_w = (const float*)d_in[2];
    const float* w1       = (const float*)d_in[3];
    const float* w2       = (const float*)d_in[4];
    const float* lns      = (const float*)d_in[5];
    float* out = (float*)d_out;

    float *p_eout;
    __half *p_xinh, *p_xinl, *p_midh, *p_midl, *p_w1h, *p_w1l, *p_w2h, *p_w2l;
    __half *p_hnh, *p_ewh;
    int   *p_counts;
    cudaGetSymbolAddress((void**)&p_eout,   g_eout);
    cudaGetSymbolAddress((void**)&p_xinh,   g_xinh);
    cudaGetSymbolAddress((void**)&p_xinl,   g_xinl);
    cudaGetSymbolAddress((void**)&p_midh,   g_midh);
    cudaGetSymbolAddress((void**)&p_midl,   g_midl);
    cudaGetSymbolAddress((void**)&p_w1h,    g_w1h);
    cudaGetSymbolAddress((void**)&p_w1l,    g_w1l);
    cudaGetSymbolAddress((void**)&p_w2h,    g_w2h);
    cudaGetSymbolAddress((void**)&p_w2l,    g_w2l);
    cudaGetSymbolAddress((void**)&p_hnh,    g_hnh);
    cudaGetSymbolAddress((void**)&p_ewh,    g_ewh);
    cudaGetSymbolAddress((void**)&p_counts, g_counts);

    cudaFuncSetAttribute(hgemm_ps<1,1>, cudaFuncAttributeMaxDynamicSharedMemorySize, HGEMM_SMEM);
    cudaFuncSetAttribute(hgemm_ps<0,0>, cudaFuncAttributeMaxDynamicSharedMemorySize, HGEMM_SMEM);
    cudaFuncSetAttribute(hgemm_logits, cudaFuncAttributeMaxDynamicSharedMemorySize, LGEMM_SMEM);

    rope_init_kernel<<<cT, 64>>>();
    embed_gather_kernel<<<(int)(((long)cT * cD + 255) / 256), 256>>>(ids, embed_w);

    // one-time operand preparation
    split_transpose_kernel<<<dim3(cDFF / 32, cD / 32, cE), dim3(32, 8)>>>(w1, p_w1h, p_w1l, cD, cDFF);
    split_transpose_kernel<<<dim3(cD / 32, cDFF / 32, cE), dim3(32, 8)>>>(w2, p_w2h, p_w2l, cDFF, cD);
    ew_half_kernel<<<(int)(((long)cV * cD / 2 + 255) / 256), 256>>>(embed_w);

    for (int hop = 0; hop < cHOPS; hop++) {
        router_logits_kernel<<<cT, 512>>>(router_w + (long)hop * cD * cE);
        token_route_kernel<<<(cT + 255) / 256, 256>>>();
        capacity_kernel<<<cE, 256>>>();
        gather_rope_kernel<<<dim3(cCAP, cE), 256>>>();
        // mid(h/l) = gelu(xin @ w1^T): M=cnt_e, N=4096, K=1024
        hgemm_ps<1,1><<<dim3(cDFF / 128, cCAP / 128, cE), 256, HGEMM_SMEM>>>(
            p_xinh, p_xinl, p_w1h, p_w1l,
            nullptr, p_midh, p_midl,
            cD, cDFF,
            (long)cCAP * cD, (long)cDFF * cD, (long)cCAP * cDFF, p_counts);
        // eout = mid @ w2^T: M=cnt_e, N=1024, K=4096
        hgemm_ps<0,0><<<dim3(cD / 128, cCAP / 128, cE), 256, HGEMM_SMEM>>>(
            p_midh, p_midl, p_w2h, p_w2l,
            p_eout, nullptr, nullptr,
            cDFF, cD,
            (long)cCAP * cDFF, (long)cD * cDFF, (long)cCAP * cD, p_counts);
        combine_kernel<<<cT, 256>>>();
    }

    rmsnorm_kernel<<<cT, 256>>>(lns);
    // logits = hn @ embed_w^T: M=2048, N=32000, K=1024, fp16 single-pass
    hgemm_logits<<<dim3(cV / 128, cT / 128, 1), 256, LGEMM_SMEM>>>(
        p_hnh, p_ewh, out, cD, cV);
}

// round 8
// speedup vs baseline: 3.4040x; 1.0890x over previous
#include <cuda_runtime.h>
#include <cuda_fp16.h>
#include <math.h>
#include <stdint.h>

// ---------------- problem constants ----------------
constexpr int cT   = 2048;
constexpr int cD   = 1024;
constexpr int cV   = 32000;
constexpr int cE   = 16;
constexpr int cK   = 2;
constexpr int cCAP = 512;
constexpr int cDH  = 64;
constexpr int cDFF = 4096;
constexpr int cHOPS= 2;

// ---------------- device scratch ----------------
__device__ float g_h   [cT * cD];
__device__ float g_cos [cT * cDH];
__device__ float g_sin [cT * cDH];
__device__ float g_logits[cT * cE];
__device__ float g_probs [cT * cE];
__device__ unsigned char g_mask[cT * cE];
__device__ int   g_kept_slot[cT * cE];
__device__ int   g_counts[cE];
__device__ int   g_etok[cE * cCAP];
__device__ float g_eout[(long)cE * cCAP * cD];
// pre-split fp16 hi/lo operands (K-contiguous rows)
__device__ __half g_xinh[(long)cE * cCAP * cD];
__device__ __half g_xinl[(long)cE * cCAP * cD];
__device__ __half g_midh[(long)cE * cCAP * cDFF];
__device__ __half g_midl[(long)cE * cCAP * cDFF];
__device__ __half g_w1h [(long)cE * cDFF * cD];   // [e][n][k]
__device__ __half g_w1l [(long)cE * cDFF * cD];
__device__ __half g_w2h [(long)cE * cD * cDFF];   // [e][n][k]
__device__ __half g_w2l [(long)cE * cD * cDFF];
// fp16 operands for logits GEMM
__device__ __half g_hnh [cT * cD];                // normalized hidden, fp16
__device__ __half g_ewh [(long)cV * cD];          // embed weights, fp16 [V][K]

// ---------------- common helpers ----------------
__device__ __forceinline__ uint32_t s2u(const void* p) {
    uint32_t a;
    asm("{ .reg .u64 t; cvta.to.shared.u64 t, %1; cvt.u32.u64 %0, t; }" : "=r"(a) : "l"(p));
    return a;
}
__device__ __forceinline__ void mma16816(float& c0, float& c1, float& c2, float& c3,
                                         uint32_t a0, uint32_t a1, uint32_t a2, uint32_t a3,
                                         uint32_t b0, uint32_t b1) {
    asm volatile(
        "mma.sync.aligned.m16n8k16.row.col.f32.f16.f16.f32 "
        "{%0,%1,%2,%3}, {%4,%5,%6,%7}, {%8,%9}, {%0,%1,%2,%3};"
        : "+f"(c0), "+f"(c1), "+f"(c2), "+f"(c3)
        : "r"(a0), "r"(a1), "r"(a2), "r"(a3), "r"(b0), "r"(b1));
}
__device__ __forceinline__ void cpa16(uint32_t dst, const void* src, int sz) {
    asm volatile("cp.async.cg.shared.global [%0], [%1], 16, %2;"
                 :: "r"(dst), "l"(src), "r"(sz) : "memory");
}
__device__ __forceinline__ void split_h(float x, __half& hi, __half& lo) {
    hi = __float2half_rn(x);
    lo = __float2half_rn(x - __half2float(hi));
}
__device__ __forceinline__ float gelu1(float x) {
    return 0.5f * x * (1.0f + tanhf(0.7978845608028654f * (x + 0.044715f * x * x * x)));
}

// ---------------- small kernels ----------------
__global__ void rope_init_kernel() {
    int t = blockIdx.x;
    int i = threadIdx.x;
    int j = 2 * (i & 31);
    float inv = powf(10000.0f, -(float)j / (float)cDH);
    float fr  = (float)t * inv;
    g_cos[t * cDH + i] = cosf(fr);
    g_sin[t * cDH + i] = sinf(fr);
}

__global__ void embed_gather_kernel(const int* __restrict__ ids,
                                    const float* __restrict__ ew) {
    long idx = (long)blockIdx.x * blockDim.x + threadIdx.x;
    if (idx >= (long)cT * cD) return;
    int t = (int)(idx >> 10);
    int d = (int)(idx & (cD - 1));
    g_h[idx] = ew[(long)ids[t] * cD + d];
}

__global__ void ew_half_kernel(const float* __restrict__ ew) {
    long idx = ((long)blockIdx.x * blockDim.x + threadIdx.x) * 2;
    if (idx >= (long)cV * cD) return;
    float2 v = *(const float2*)&ew[idx];
    *(__half2*)&g_ewh[idx] = __halves2half2(__float2half_rn(v.x), __float2half_rn(v.y));
}

__global__ void router_logits_kernel(const float* __restrict__ wr) {
    int t    = blockIdx.x;
    int e    = threadIdx.x >> 5;
    int lane = threadIdx.x & 31;
    float s = 0.f;
    const float* hp = &g_h[(long)t * cD];
    for (int d = lane; d < cD; d += 32)
        s += hp[d] * wr[(long)d * cE + e];
    #pragma unroll
    for (int o = 16; o; o >>= 1) s += __shfl_down_sync(0xffffffffu, s, o);
    if (lane == 0) g_logits[t * cE + e] = s;
}

__global__ void token_route_kernel() {
    int t = blockIdx.x * blockDim.x + threadIdx.x;
    if (t >= cT) return;
    float l[cE];
    #pragma unroll
    for (int e = 0; e < cE; e++) l[e] = g_logits[t * cE + e];
    int i1 = 0; float v1 = l[0];
    #pragma unroll
    for (int e = 1; e < cE; e++) if (l[e] > v1) { v1 = l[e]; i1 = e; }
    int i2 = -1; float v2 = -INFINITY;
    #pragma unroll
    for (int e = 0; e < cE; e++) if (e != i1 && l[e] > v2) { v2 = l[e]; i2 = e; }
    float sum = 0.f; float p[cE];
    #pragma unroll
    for (int e = 0; e < cE; e++) { p[e] = expf(l[e] - v1); sum += p[e]; }
    float invs = 1.0f / sum;
    #pragma unroll
    for (int e = 0; e < cE; e++) {
        g_probs[t * cE + e] = p[e] * invs;
        g_mask [t * cE + e] = (e == i1 || e == i2) ? 1 : 0;
        g_kept_slot[t * cE + e] = -1;
    }
    if (t < cE) g_counts[t] = 0;
}

__global__ void capacity_kernel() {
    int e = blockIdx.x;
    __shared__ int   cnt;
    __shared__ int   idx[cT];
    __shared__ float val[cT];
    if (threadIdx.x == 0) cnt = 0;
    __syncthreads();
    for (int t = threadIdx.x; t < cT; t += blockDim.x) {
        if (g_mask[t * cE + e]) {
            int p = atomicAdd(&cnt, 1);
            idx[p] = t;
            val[p] = g_logits[t * cE + e];
        }
    }
    __syncthreads();
    int n = cnt;
    for (int i = threadIdx.x; i < n; i += blockDim.x) {
        float v = val[i]; int t = idx[i];
        int rank = 0;
        for (int j = 0; j < n; j++) {
            float u = val[j]; int s = idx[j];
            rank += (u > v || (u == v && s < t)) ? 1 : 0;
        }
        if (rank < cCAP) {
            int slot = atomicAdd(&g_counts[e], 1);
            g_etok[e * cCAP + slot] = t;
            g_kept_slot[t * cE + e] = slot;
        }
    }
}

// gather + RoPE + fp16 hi/lo split (pairs of adjacent d)
__global__ void gather_rope_kernel() {
    int c = blockIdx.x;
    int e = blockIdx.y;
    if (c >= g_counts[e]) return;
    int t = g_etok[e * cCAP + c];
    __shared__ float x[cD];
    for (int d = threadIdx.x; d < cD; d += blockDim.x) x[d] = g_h[(long)t * cD + d];
    __syncthreads();
    const float* cs = &g_cos[t * cDH];
    const float* sn = &g_sin[t * cDH];
    long base = ((long)(e * cCAP + c)) * cD;
    for (int dp = threadIdx.x; dp < cD / 2; dp += blockDim.x) {
        int d0 = dp * 2;
        float o[2];
        #pragma unroll
        for (int q = 0; q < 2; q++) {
            int d = d0 + q;
            int i = d & (cDH - 1);
            float r = (i < 32) ? -x[d + 32] : x[d - 32];
            o[q] = x[d] * cs[i] + r * sn[i];
        }
        __half h0, l0, h1, l1;
        split_h(o[0], h0, l0);
        split_h(o[1], h1, l1);
        *(__half2*)&g_xinh[base + d0] = __halves2half2(h0, h1);
        *(__half2*)&g_xinl[base + d0] = __halves2half2(l0, l1);
    }
}

__global__ void combine_kernel() {
    int t = blockIdx.x;
    int ne = 0;
    int ks[cK]; float kp[cK]; int ke[cK];
    float rho = 0.f;
    #pragma unroll
    for (int e = 0; e < cE; e++) {
        int s = g_kept_slot[t * cE + e];
        if (s >= 0) {
            float p = g_probs[t * cE + e];
            rho += p;
            if (ne < cK) { ke[ne] = e; ks[ne] = s; kp[ne] = p; ne++; }
        }
    }
    for (int d = threadIdx.x; d < cD; d += blockDim.x) {
        float hv = g_h[(long)t * cD + d];
        float comb = 0.f;
        for (int q = 0; q < ne; q++)
            comb += kp[q] * g_eout[((long)(ke[q] * cCAP + ks[q])) * cD + d];
        g_h[(long)t * cD + d] = hv + comb - rho * hv;
    }
}

// RMSNorm -> fp16 output for logits GEMM
__global__ void rmsnorm_kernel(const float* __restrict__ lns) {
    int t = blockIdx.x;
    __shared__ float red[256];
    float s = 0.f;
    for (int d = threadIdx.x; d < cD; d += 256) {
        float v = g_h[(long)t * cD + d];
        s += v * v;
    }
    red[threadIdx.x] = s;
    __syncthreads();
    #pragma unroll
    for (int o = 128; o; o >>= 1) {
        if (threadIdx.x < o) red[threadIdx.x] += red[threadIdx.x + o];
        __syncthreads();
    }
    float inv = rsqrtf(red[0] / (float)cD + 1e-6f);
    for (int d = threadIdx.x; d < cD; d += 256)
        g_hnh[(long)t * cD + d] =
            __float2half_rn(g_h[(long)t * cD + d] * lns[d] * inv);
}

// pre-split + transpose weights: in [R][C] fp32 (R=K rows) -> oh/ol [C][R] fp16
__global__ void split_transpose_kernel(const float* __restrict__ in,
                                       __half* __restrict__ oh, __half* __restrict__ ol,
                                       int R, int C) {
    __shared__ float tile[32][33];
    long eoff = (long)blockIdx.z * R * C;
    int c0 = blockIdx.x * 32, r0 = blockIdx.y * 32;
    int x = threadIdx.x, y = threadIdx.y;       // 32 x 8
    #pragma unroll
    for (int i = 0; i < 32; i += 8)
        tile[y + i][x] = in[eoff + (long)(r0 + y + i) * C + c0 + x];
    __syncthreads();
    if (x < 16) {
        #pragma unroll
        for (int i = 0; i < 32; i += 8) {
            int nl = y + i;
            float v0 = tile[2 * x][nl];
            float v1 = tile[2 * x + 1][nl];
            __half h0, l0, h1, l1;
            split_h(v0, h0, l0);
            split_h(v1, h1, l1);
            long o = eoff + (long)(c0 + nl) * R + r0 + 2 * x;
            *(__half2*)&oh[o] = __halves2half2(h0, h1);
            *(__half2*)&ol[o] = __halves2half2(l0, l1);
        }
    }
}

// ---------------- pre-split fp16 GEMM (experts) ----------------
// NPASS=3: ah*bh + ah*bl + al*bh (fp32-class, routing-safe)
// NPASS=2: ah*bh + ah*bl        (A rounded to fp16; for final hop only)
constexpr int HSTR  = 20;                    // b32 row stride (16 used + 4 pad)
constexpr int HSEG  = 128 * HSTR;            // 2560 b32
constexpr int HSTAGE= 4 * HSEG;              // Ahi Alo Bhi Blo
constexpr int HGEMM_SMEM = 2 * HSTAGE * 4;   // 81920 B

template<int ACT, int OUTF16, int NPASS>
__global__ void __launch_bounds__(256, 1)
hgemm_ps(const __half* __restrict__ Ah, const __half* __restrict__ Al,
         const __half* __restrict__ Bh, const __half* __restrict__ Bl,
         float* __restrict__ Cf, __half* __restrict__ Ch, __half* __restrict__ Cl,
         int Kd, int ldc,
         long sA, long sB, long sC, const int* __restrict__ Mvec)
{
    extern __shared__ uint32_t sh[];
    int e  = blockIdx.z;
    int Me = Mvec[e];
    int bm = blockIdx.y * 128;
    if (bm >= Me) return;
    int bn = blockIdx.x * 128;
    const __half* Ahp = Ah + (long)e * sA;
    const __half* Alp = Al + (long)e * sA;
    const __half* Bhp = Bh + (long)e * sB;
    const __half* Blp = Bl + (long)e * sB;

    int tid = threadIdx.x;
    int wid = tid >> 5, lane = tid & 31;
    int g   = lane >> 2, tg = lane & 3;
    int wm  = (wid & 3) * 32;
    int wn  = (wid >> 2) * 64;

    uint32_t smu = s2u(sh);

    auto load_stage = [&](int s, int k0) {
        uint32_t b0 = smu + (s * HSTAGE) * 4;
        #pragma unroll
        for (int j = 0; j < 2; j++) {
            int q = tid + 256 * j;
            int row = q >> 2, c4 = q & 3;
            int ok = (bm + row) < Me;
            long so = (long)(bm + row) * Kd + k0 + c4 * 8;
            uint32_t doff = (row * HSTR + c4 * 4) * 4;
            cpa16(b0 + doff, Ahp + so, ok ? 16 : 0);
            if (NPASS == 3)
                cpa16(b0 + HSEG * 4 + doff, Alp + so, ok ? 16 : 0);
        }
        #pragma unroll
        for (int j = 0; j < 2; j++) {
            int q = tid + 256 * j;
            int row = q >> 2, c4 = q & 3;
            long so = (long)(bn + row) * Kd + k0 + c4 * 8;
            uint32_t doff = (row * HSTR + c4 * 4) * 4;
            cpa16(b0 + HSEG * 8 + doff,  Bhp + so, 16);
            cpa16(b0 + HSEG * 12 + doff, Blp + so, 16);
        }
        asm volatile("cp.async.commit_group;" ::: "memory");
    };

    float c[2][8][4];
    #pragma unroll
    for (int mi = 0; mi < 2; mi++)
        #pragma unroll
        for (int ni = 0; ni < 8; ni++)
            #pragma unroll
            for (int q = 0; q < 4; q++) c[mi][ni][q] = 0.f;

    int nK = Kd >> 5;
    load_stage(0, 0);
    load_stage(1, 32);

    for (int i = 0; i < nK; i++) {
        asm volatile("cp.async.wait_group 1;" ::: "memory");
        __syncthreads();

        const uint32_t* Ahi = sh + (i & 1) * HSTAGE;
        const uint32_t* Alo = Ahi + HSEG;
        const uint32_t* Bhi = Alo + HSEG;
        const uint32_t* Blo = Bhi + HSEG;

        #pragma unroll
        for (int ks = 0; ks < 2; ks++) {
            int ko = ks * 8;
            uint32_t ah[2][4], al[2][4];
            #pragma unroll
            for (int mi = 0; mi < 2; mi++) {
                int r0 = wm + mi * 16 + g;
                int o0 = r0 * HSTR + ko + tg;
                int o1 = (r0 + 8) * HSTR + ko + tg;
                ah[mi][0] = Ahi[o0];     ah[mi][1] = Ahi[o1];
                ah[mi][2] = Ahi[o0 + 4]; ah[mi][3] = Ahi[o1 + 4];
                if (NPASS == 3) {
                    al[mi][0] = Alo[o0];     al[mi][1] = Alo[o1];
                    al[mi][2] = Alo[o0 + 4]; al[mi][3] = Alo[o1 + 4];
                }
            }
            uint32_t bh[8][2], bl[8][2];
            #pragma unroll
            for (int ni = 0; ni < 8; ni++) {
                int n = wn + ni * 8 + g;
                int o = n * HSTR + ko + tg;
                bh[ni][0] = Bhi[o]; bh[ni][1] = Bhi[o + 4];
                bl[ni][0] = Blo[o]; bl[ni][1] = Blo[o + 4];
            }
            #pragma unroll
            for (int mi = 0; mi < 2; mi++)
                #pragma unroll
                for (int ni = 0; ni < 8; ni++)
                    mma16816(c[mi][ni][0], c[mi][ni][1], c[mi][ni][2], c[mi][ni][3],
                             ah[mi][0], ah[mi][1], ah[mi][2], ah[mi][3],
                             bh[ni][0], bh[ni][1]);
            #pragma unroll
            for (int mi = 0; mi < 2; mi++)
                #pragma unroll
                for (int ni = 0; ni < 8; ni++)
                    mma16816(c[mi][ni][0], c[mi][ni][1], c[mi][ni][2], c[mi][ni][3],
                             ah[mi][0], ah[mi][1], ah[mi][2], ah[mi][3],
                             bl[ni][0], bl[ni][1]);
            if (NPASS == 3) {
                #pragma unroll
                for (int mi = 0; mi < 2; mi++)
                    #pragma unroll
                    for (int ni = 0; ni < 8; ni++)
                        mma16816(c[mi][ni][0], c[mi][ni][1], c[mi][ni][2], c[mi][ni][3],
                                 al[mi][0], al[mi][1], al[mi][2], al[mi][3],
                                 bh[ni][0], bh[ni][1]);
            }
        }
        __syncthreads();
        if (i + 2 < nK) load_stage(i & 1, (i + 2) * 32);
        else asm volatile("cp.async.commit_group;" ::: "memory");
    }

    #pragma unroll
    for (int mi = 0; mi < 2; mi++) {
        int r0 = bm + wm + mi * 16 + g;
        #pragma unroll
        for (int ni = 0; ni < 8; ni++) {
            int col = bn + wn + ni * 8 + tg * 2;
            float v0 = c[mi][ni][0], v1 = c[mi][ni][1];
            float v2 = c[mi][ni][2], v3 = c[mi][ni][3];
            if (ACT) { v0 = gelu1(v0); v1 = gelu1(v1); v2 = gelu1(v2); v3 = gelu1(v3); }
            if (OUTF16) {
                __half h0, l0, h1, l1;
                if (r0 < Me) {
                    split_h(v0, h0, l0); split_h(v1, h1, l1);
                    long o = (long)e * sC + (long)r0 * ldc + col;
                    *(__half2*)&Ch[o] = __halves2half2(h0, h1);
                    *(__half2*)&Cl[o] = __halves2half2(l0, l1);
                }
                if (r0 + 8 < Me) {
                    split_h(v2, h0, l0); split_h(v3, h1, l1);
                    long o = (long)e * sC + (long)(r0 + 8) * ldc + col;
                    *(__half2*)&Ch[o] = __halves2half2(h0, h1);
                    *(__half2*)&Cl[o] = __halves2half2(l0, l1);
                }
            } else {
                long eb = (long)e * sC;
                if (r0 < Me)     *(float2*)&Cf[eb + (long)r0 * ldc + col]       = make_float2(v0, v1);
                if (r0 + 8 < Me) *(float2*)&Cf[eb + (long)(r0 + 8) * ldc + col] = make_float2(v2, v3);
            }
        }
    }
}

// ---------------- fp16 single-pass GEMM for logits ----------------
constexpr int LSTAGE = 2 * HSEG;                 // Ah + Bh
constexpr int LGEMM_SMEM = 2 * LSTAGE * 4;       // 40960 B

__global__ void __launch_bounds__(256, 2)
hgemm_logits(const __half* __restrict__ A, const __half* __restrict__ B,
             float* __restrict__ C, int Kd, int ldc)
{
    extern __shared__ uint32_t sh[];
    int bm = blockIdx.y * 128;
    int bn = blockIdx.x * 128;

    int tid = threadIdx.x;
    int wid = tid >> 5, lane = tid & 31;
    int g   = lane >> 2, tg = lane & 3;
    int wm  = (wid & 3) * 32;
    int wn  = (wid >> 2) * 64;

    uint32_t smu = s2u(sh);

    auto load_stage = [&](int s, int k0) {
        uint32_t b0 = smu + (s * LSTAGE) * 4;
        #pragma unroll
        for (int j = 0; j < 2; j++) {
            int q = tid + 256 * j;
            int row = q >> 2, c4 = q & 3;
            uint32_t doff = (row * HSTR + c4 * 4) * 4;
            cpa16(b0 + doff,            A + (long)(bm + row) * Kd + k0 + c4 * 8, 16);
            cpa16(b0 + HSEG * 4 + doff, B + (long)(bn + row) * Kd + k0 + c4 * 8, 16);
        }
        asm volatile("cp.async.commit_group;" ::: "memory");
    };

    float c[2][8][4];
    #pragma unroll
    for (int mi = 0; mi < 2; mi++)
        #pragma unroll
        for (int ni = 0; ni < 8; ni++)
            #pragma unroll
            for (int q = 0; q < 4; q++) c[mi][ni][q] = 0.f;

    int nK = Kd >> 5;
    load_stage(0, 0);
    load_stage(1, 32);

    for (int i = 0; i < nK; i++) {
        asm volatile("cp.async.wait_group 1;" ::: "memory");
        __syncthreads();

        const uint32_t* As = sh + (i & 1) * LSTAGE;
        const uint32_t* Bs = As + HSEG;

        #pragma unroll
        for (int ks = 0; ks < 2; ks++) {
            int ko = ks * 8;
            uint32_t a[2][4], b[8][2];
            #pragma unroll
            for (int mi = 0; mi < 2; mi++) {
                int r0 = wm + mi * 16 + g;
                int o0 = r0 * HSTR + ko + tg;
                int o1 = (r0 + 8) * HSTR + ko + tg;
                a[mi][0] = As[o0];     a[mi][1] = As[o1];
                a[mi][2] = As[o0 + 4]; a[mi][3] = As[o1 + 4];
            }
            #pragma unroll
            for (int ni = 0; ni < 8; ni++) {
                int n = wn + ni * 8 + g;
                int o = n * HSTR + ko + tg;
                b[ni][0] = Bs[o]; b[ni][1] = Bs[o + 4];
            }
            #pragma unroll
            for (int mi = 0; mi < 2; mi++)
                #pragma unroll
                for (int ni = 0; ni < 8; ni++)
                    mma16816(c[mi][ni][0], c[mi][ni][1], c[mi][ni][2], c[mi][ni][3],
                             a[mi][0], a[mi][1], a[mi][2], a[mi][3],
                             b[ni][0], b[ni][1]);
        }
        __syncthreads();
        if (i + 2 < nK) load_stage(i & 1, (i + 2) * 32);
        else asm volatile("cp.async.commit_group;" ::: "memory");
    }

    #pragma unroll
    for (int mi = 0; mi < 2; mi++) {
        int r0 = bm + wm + mi * 16 + g;
        #pragma unroll
        for (int ni = 0; ni < 8; ni++) {
            int col = bn + wn + ni * 8 + tg * 2;
            *(float2*)&C[(long)r0 * ldc + col]       = make_float2(c[mi][ni][0], c[mi][ni][1]);
            *(float2*)&C[(long)(r0 + 8) * ldc + col] = make_float2(c[mi][ni][2], c[mi][ni][3]);
        }
    }
}

// ---------------- launch ----------------
extern "C" void kernel_launch(void* const* d_in, const int* in_sizes, int n_in,
                              void* d_out, int out_size) {
    const int*   ids      = (const int*)  d_in[0];
    const float* embed_w  = (const float*)d_in[1];
    const float* router_w = (const float*)d_in[2];
    const float* w1       = (const float*)d_in[3];
    const float* w2       = (const float*)d_in[4];
    const float* lns      = (const float*)d_in[5];
    float* out = (float*)d_out;

    float *p_eout;
    __half *p_xinh, *p_xinl, *p_midh, *p_midl, *p_w1h, *p_w1l, *p_w2h, *p_w2l;
    __half *p_hnh, *p_ewh;
    int   *p_counts;
    cudaGetSymbolAddress((void**)&p_eout,   g_eout);
    cudaGetSymbolAddress((void**)&p_xinh,   g_xinh);
    cudaGetSymbolAddress((void**)&p_xinl,   g_xinl);
    cudaGetSymbolAddress((void**)&p_midh,   g_midh);
    cudaGetSymbolAddress((void**)&p_midl,   g_midl);
    cudaGetSymbolAddress((void**)&p_w1h,    g_w1h);
    cudaGetSymbolAddress((void**)&p_w1l,    g_w1l);
    cudaGetSymbolAddress((void**)&p_w2h,    g_w2h);
    cudaGetSymbolAddress((void**)&p_w2l,    g_w2l);
    cudaGetSymbolAddress((void**)&p_hnh,    g_hnh);
    cudaGetSymbolAddress((void**)&p_ewh,    g_ewh);
    cudaGetSymbolAddress((void**)&p_counts, g_counts);

    cudaFuncSetAttribute(hgemm_ps<1,1,3>, cudaFuncAttributeMaxDynamicSharedMemorySize, HGEMM_SMEM);
    cudaFuncSetAttribute(hgemm_ps<0,0,3>, cudaFuncAttributeMaxDynamicSharedMemorySize, HGEMM_SMEM);
    cudaFuncSetAttribute(hgemm_ps<1,1,2>, cudaFuncAttributeMaxDynamicSharedMemorySize, HGEMM_SMEM);
    cudaFuncSetAttribute(hgemm_ps<0,0,2>, cudaFuncAttributeMaxDynamicSharedMemorySize, HGEMM_SMEM);
    cudaFuncSetAttribute(hgemm_logits, cudaFuncAttributeMaxDynamicSharedMemorySize, LGEMM_SMEM);

    rope_init_kernel<<<cT, 64>>>();
    embed_gather_kernel<<<(int)(((long)cT * cD + 255) / 256), 256>>>(ids, embed_w);

    // one-time operand preparation
    split_transpose_kernel<<<dim3(cDFF / 32, cD / 32, cE), dim3(32, 8)>>>(w1, p_w1h, p_w1l, cD, cDFF);
    split_transpose_kernel<<<dim3(cD / 32, cDFF / 32, cE), dim3(32, 8)>>>(w2, p_w2h, p_w2l, cDFF, cD);
    ew_half_kernel<<<(int)(((long)cV * cD / 2 + 255) / 256), 256>>>(embed_w);

    for (int hop = 0; hop < cHOPS; hop++) {
        router_logits_kernel<<<cT, 512>>>(router_w + (long)hop * cD * cE);
        token_route_kernel<<<(cT + 255) / 256, 256>>>();
        capacity_kernel<<<cE, 256>>>();
        gather_rope_kernel<<<dim3(cCAP, cE), 256>>>();
        if (hop == 0) {
            // routing-critical hop: full 3-pass precision
            hgemm_ps<1,1,3><<<dim3(cDFF / 128, cCAP / 128, cE), 256, HGEMM_SMEM>>>(
                p_xinh, p_xinl, p_w1h, p_w1l,
                nullptr, p_midh, p_midl,
                cD, cDFF,
                (long)cCAP * cD, (long)cDFF * cD, (long)cCAP * cDFF, p_counts);
            hgemm_ps<0,0,3><<<dim3(cD / 128, cCAP / 128, cE), 256, HGEMM_SMEM>>>(
                p_midh, p_midl, p_w2h, p_w2l,
                p_eout, nullptr, nullptr,
                cDFF, cD,
                (long)cCAP * cDFF, (long)cD * cDFF, (long)cCAP * cD, p_counts);
        } else {
            // final hop: feeds only logits — 2-pass suffices
            hgemm_ps<1,1,2><<<dim3(cDFF / 128, cCAP / 128, cE), 256, HGEMM_SMEM>>>(
                p_xinh, p_xinl, p_w1h, p_w1l,
                nullptr, p_midh, p_midl,
                cD, cDFF,
                (long)cCAP * cD, (long)cDFF * cD, (long)cCAP * cDFF, p_counts);
            hgemm_ps<0,0,2><<<dim3(cD / 128, cCAP / 128, cE), 256, HGEMM_SMEM>>>(
                p_midh, p_midl, p_w2h, p_w2l,
                p_eout, nullptr, nullptr,
                cDFF, cD,
                (long)cCAP * cDFF, (long)cD * cDFF, (long)cCAP * cD, p_counts);
        }
        combine_kernel<<<cT, 256>>>();
    }

    rmsnorm_kernel<<<cT, 256>>>(lns);
    // logits = hn @ embed_w^T: M=2048, N=32000, K=1024, fp16 single-pass
    hgemm_logits<<<dim3(cV / 128, cT / 128, 1), 256, LGEMM_SMEM>>>(
        p_hnh, p_ewh, out, cD, cV);
}